// round 3
// baseline (speedup 1.0000x reference)
#include <cuda_runtime.h>
#include <math.h>

#define NN 100000
#define EE 1000000
#define NB1 98   // ceil(NN/1024)

// ---------------- scratch (static device globals; no allocation) -------------
__device__ float g_h128[(size_t)NN*128];   // per-layer features (N,2,64)
__device__ float g_buf64[(size_t)NN*64];   // aggregation output / MLP hidden
__device__ float g_as[NN*2];
__device__ float g_ad[NN*2];
__device__ int   g_deg[NN];                // zero-init at load; re-zeroed by k_scatter
__device__ int   g_off[NN];                // inclusive scan of degrees
__device__ int   g_cursor[NN];
__device__ int   g_esrc[EE];               // src index sorted by dst
__device__ int   g_bsum[128];
__device__ float g_part[128*128];          // per-block BN partials: [block][sum64|sumsq64]
__device__ float g_bnscale[64];
__device__ float g_bnshift[64];
__device__ int   g_bncnt;

__device__ __forceinline__ float lrelu(float v){ return v > 0.f ? v : 0.2f*v; }

// ---------------- CSR build --------------------------------------------------
__global__ void k_count(const int* __restrict__ ei){
  int e = blockIdx.x*blockDim.x + threadIdx.x;
  if (e < EE) atomicAdd(&g_deg[ei[EE + e]], 1);
}

__global__ void k_scan1(){
  __shared__ int s[256];
  int tid = threadIdx.x;
  int base = blockIdx.x*1024 + tid*4;
  int v[4]; int loc = 0;
  #pragma unroll
  for (int i = 0; i < 4; i++){ int idx = base + i; v[i] = (idx < NN) ? g_deg[idx] : 0; loc += v[i]; }
  s[tid] = loc; __syncthreads();
  #pragma unroll
  for (int d = 1; d < 256; d <<= 1){
    int t = (tid >= d) ? s[tid-d] : 0; __syncthreads();
    s[tid] += t; __syncthreads();
  }
  int run = (tid == 0) ? 0 : s[tid-1];
  #pragma unroll
  for (int i = 0; i < 4; i++){ run += v[i]; int idx = base + i; if (idx < NN) g_off[idx] = run; }
  if (tid == 255) g_bsum[blockIdx.x] = s[255];
}

// fused scan2 + scan3 + cursor: each block sums the block-sums before it
__global__ void k_scan23c(){
  int tid = threadIdx.x;
  int b = blockIdx.x;
  __shared__ int swarp[8];
  int v = (tid < b) ? g_bsum[tid] : 0;     // b <= 97 < 128
  #pragma unroll
  for (int o = 16; o; o >>= 1) v += __shfl_xor_sync(0xffffffffu, v, o);
  if ((tid & 31) == 0) swarp[tid >> 5] = v;
  __syncthreads();
  int pre = swarp[0] + swarp[1] + swarp[2] + swarp[3];
  int base = b*1024 + tid*4;
  #pragma unroll
  for (int i = 0; i < 4; i++){
    int idx = base + i;
    if (idx < NN){
      int off = g_off[idx] + pre;
      g_off[idx] = off;
      g_cursor[idx] = off - g_deg[idx];
    }
  }
}

__global__ void k_scatter(const int* __restrict__ ei){
  int e = blockIdx.x*blockDim.x + threadIdx.x;
  if (e < EE){
    int s = ei[e], d = ei[EE + e];
    int pos = atomicAdd(&g_cursor[d], 1);
    g_esrc[pos] = s;
  }
  if (e < NN) g_deg[e] = 0;   // re-zero for next replay (deg is dead by now)
}

// ---------------- GEMM + fused BN-in + fused attprep-out ---------------------
// BN=true: read g_buf64, apply per-channel scale/shift + relu at load.
// Epilogue: a_s[n,h], a_d[n,h] computed from the h row in registers.
template<int DIN, bool BN>
__global__ void __launch_bounds__(256) k_gemm(const float* __restrict__ Xin,
                                              const float* __restrict__ W,
                                              const float* __restrict__ aw,
                                              const float* __restrict__ dw){
  const float* X = BN ? (const float*)g_buf64 : Xin;
  int j = threadIdx.x & 127;
  int g = threadIdx.x >> 7;
  float wreg[DIN];
  #pragma unroll
  for (int k = 0; k < DIN; k++) wreg[k] = W[k*128 + j];
  float awj = aw[j], dwj = dw[j];
  float4 sc4, sh4;
  if (BN && j < DIN/4){
    sc4 = ((const float4*)g_bnscale)[j];
    sh4 = ((const float4*)g_bnshift)[j];
  }
  __shared__ __align__(16) float4 sx[2][DIN/4];
  __shared__ float sas[2][4], sad[2][4];
  for (int n0 = blockIdx.x*2; n0 < NN; n0 += gridDim.x*2){
    int n = n0 + g;
    if (n < NN && j < DIN/4){
      float4 v = ((const float4*)(X + (size_t)n*DIN))[j];
      if (BN){
        v.x = fmaxf(v.x*sc4.x + sh4.x, 0.f);
        v.y = fmaxf(v.y*sc4.y + sh4.y, 0.f);
        v.z = fmaxf(v.z*sc4.z + sh4.z, 0.f);
        v.w = fmaxf(v.w*sc4.w + sh4.w, 0.f);
      }
      sx[g][j] = v;
    }
    __syncthreads();
    float res = 0.f;
    if (n < NN){
      float acc0 = 0.f, acc1 = 0.f, acc2 = 0.f, acc3 = 0.f;
      #pragma unroll
      for (int k = 0; k < DIN/4; k++){
        float4 h4 = sx[g][k];
        acc0 += h4.x*wreg[4*k];   acc1 += h4.y*wreg[4*k+1];
        acc2 += h4.z*wreg[4*k+2]; acc3 += h4.w*wreg[4*k+3];
      }
      res = (acc0+acc1)+(acc2+acc3);
      g_h128[(size_t)n*128 + j] = res;
    }
    // fused attprep: warp-reduce res*aw / res*dw, combine pairs of warps
    float sc = res*awj, dc = res*dwj;
    #pragma unroll
    for (int o = 16; o; o >>= 1){
      sc += __shfl_xor_sync(0xffffffffu, sc, o);
      dc += __shfl_xor_sync(0xffffffffu, dc, o);
    }
    int w = j >> 5;
    if ((j & 31) == 0){ sas[g][w] = sc; sad[g][w] = dc; }
    __syncthreads();
    if (j == 0 && n < NN){
      g_as[2*n]   = sas[g][0] + sas[g][1];
      g_as[2*n+1] = sas[g][2] + sas[g][3];
      g_ad[2*n]   = sad[g][0] + sad[g][1];
      g_ad[2*n+1] = sad[g][2] + sad[g][3];
    }
    __syncthreads();
  }
}

// ---------------- GAT aggregation: one warp per destination node -------------
// float4 gather: one LDG.128 per edge per warp. Lane holds channels
// [4*lane..4*lane+3]; head = lane>>4. Heads combined via shfl_xor(.,16).
__global__ void __launch_bounds__(256) k_aggregate(const float* __restrict__ bias){
  int t = blockIdx.x*blockDim.x + threadIdx.x;
  int n = t >> 5, lane = t & 31;
  if (n >= NN) return;
  int start = n ? g_off[n-1] : 0;
  int end   = g_off[n];
  int len   = end - start;
  float ad0 = g_ad[2*n], ad1 = g_ad[2*n+1];
  float es0 = lrelu(g_as[2*n]   + ad0);   // self loop
  float es1 = lrelu(g_as[2*n+1] + ad1);
  const float4* hr4 = (const float4*)(g_h128 + (size_t)n*128);
  bool head0 = (lane < 16);

  float4 a;
  float den0, den1;

  if (len <= 32){
    int s = 0; float e0 = -1e30f, e1 = -1e30f;
    if (lane < len){
      s = g_esrc[start + lane];
      float2 asv = ((const float2*)g_as)[s];
      e0 = lrelu(asv.x + ad0);
      e1 = lrelu(asv.y + ad1);
    }
    float m0 = fmaxf(e0, es0), m1 = fmaxf(e1, es1);
    #pragma unroll
    for (int o = 16; o; o >>= 1){
      m0 = fmaxf(m0, __shfl_xor_sync(0xffffffffu, m0, o));
      m1 = fmaxf(m1, __shfl_xor_sync(0xffffffffu, m1, o));
    }
    float w0 = (lane < len) ? __expf(e0 - m0) : 0.f;
    float w1 = (lane < len) ? __expf(e1 - m1) : 0.f;
    float d0 = w0, d1 = w1;
    #pragma unroll
    for (int o = 16; o; o >>= 1){
      d0 += __shfl_xor_sync(0xffffffffu, d0, o);
      d1 += __shfl_xor_sync(0xffffffffu, d1, o);
    }
    float ws0 = __expf(es0 - m0), ws1 = __expf(es1 - m1);
    den0 = d0 + ws0 + 1e-16f;
    den1 = d1 + ws1 + 1e-16f;
    float4 selfv = hr4[lane];
    float mws = head0 ? ws0 : ws1;
    a.x = mws*selfv.x; a.y = mws*selfv.y; a.z = mws*selfv.z; a.w = mws*selfv.w;
    #pragma unroll 4
    for (int k = 0; k < len; k++){
      int   sk  = __shfl_sync(0xffffffffu, s,  k);
      float wk0 = __shfl_sync(0xffffffffu, w0, k);
      float wk1 = __shfl_sync(0xffffffffu, w1, k);
      float wk  = head0 ? wk0 : wk1;
      float4 v = ((const float4*)(g_h128 + (size_t)sk*128))[lane];
      a.x += wk*v.x; a.y += wk*v.y; a.z += wk*v.z; a.w += wk*v.w;
    }
  } else {
    // rare high-degree path: two passes, chunked
    float m0 = es0, m1 = es1;
    for (int i = start + lane; i < end; i += 32){
      int s = g_esrc[i];
      float2 asv = ((const float2*)g_as)[s];
      m0 = fmaxf(m0, lrelu(asv.x + ad0));
      m1 = fmaxf(m1, lrelu(asv.y + ad1));
    }
    #pragma unroll
    for (int o = 16; o; o >>= 1){
      m0 = fmaxf(m0, __shfl_xor_sync(0xffffffffu, m0, o));
      m1 = fmaxf(m1, __shfl_xor_sync(0xffffffffu, m1, o));
    }
    float ws0 = __expf(es0 - m0), ws1 = __expf(es1 - m1);
    float4 selfv = hr4[lane];
    float mws = head0 ? ws0 : ws1;
    a.x = mws*selfv.x; a.y = mws*selfv.y; a.z = mws*selfv.z; a.w = mws*selfv.w;
    float d0 = 0.f, d1 = 0.f;
    for (int base = start; base < end; base += 32){
      int cnt = min(32, end - base);
      int s = 0; float w0 = 0.f, w1 = 0.f;
      if (lane < cnt){
        s = g_esrc[base + lane];
        float2 asv = ((const float2*)g_as)[s];
        w0 = __expf(lrelu(asv.x + ad0) - m0);
        w1 = __expf(lrelu(asv.y + ad1) - m1);
      }
      d0 += w0; d1 += w1;
      for (int k = 0; k < cnt; k++){
        int   sk  = __shfl_sync(0xffffffffu, s,  k);
        float wk0 = __shfl_sync(0xffffffffu, w0, k);
        float wk1 = __shfl_sync(0xffffffffu, w1, k);
        float wk  = head0 ? wk0 : wk1;
        float4 v = ((const float4*)(g_h128 + (size_t)sk*128))[lane];
        a.x += wk*v.x; a.y += wk*v.y; a.z += wk*v.z; a.w += wk*v.w;
      }
    }
    #pragma unroll
    for (int o = 16; o; o >>= 1){
      d0 += __shfl_xor_sync(0xffffffffu, d0, o);
      d1 += __shfl_xor_sync(0xffffffffu, d1, o);
    }
    den0 = d0 + ws0 + 1e-16f;
    den1 = d1 + ws1 + 1e-16f;
  }

  // combine heads: lane l (<16) holds head0 acc for channels 4l..4l+3;
  // lane l+16 holds head1 acc for the same channels.
  float4 o4;
  o4.x = __shfl_xor_sync(0xffffffffu, a.x, 16);
  o4.y = __shfl_xor_sync(0xffffffffu, a.y, 16);
  o4.z = __shfl_xor_sync(0xffffffffu, a.z, 16);
  o4.w = __shfl_xor_sync(0xffffffffu, a.w, 16);
  if (head0){
    float i0 = 0.5f/den0, i1 = 0.5f/den1;
    float4 b4 = ((const float4*)bias)[lane];
    float4 r;
    r.x = a.x*i0 + o4.x*i1 + b4.x;
    r.y = a.y*i0 + o4.y*i1 + b4.y;
    r.z = a.z*i0 + o4.z*i1 + b4.z;
    r.w = a.w*i0 + o4.w*i1 + b4.w;
    ((float4*)(g_buf64 + (size_t)n*64))[lane] = r;
  }
}

// ---------------- batch norm stats + fused final (last-block) ----------------
__global__ void __launch_bounds__(256) k_bnstatsfinal(const float* __restrict__ gam,
                                                      const float* __restrict__ bet){
  int c = threadIdx.x & 63, g = threadIdx.x >> 6;
  float s = 0.f, q = 0.f;
  for (int n = blockIdx.x*4 + g; n < NN; n += gridDim.x*4){
    float v = g_buf64[(size_t)n*64 + c];
    s += v; q += v*v;
  }
  __shared__ float sh[256], shq[256];
  sh[threadIdx.x] = s; shq[threadIdx.x] = q; __syncthreads();
  if (g == 0){
    float ts = sh[c] + sh[c+64] + sh[c+128] + sh[c+192];
    float tq = shq[c] + shq[c+64] + shq[c+128] + shq[c+192];
    g_part[blockIdx.x*128 + c]      = ts;
    g_part[blockIdx.x*128 + 64 + c] = tq;
  }
  __threadfence();
  __shared__ bool last;
  if (threadIdx.x == 0){
    last = (atomicAdd(&g_bncnt, 1) == 127);
    if (last) g_bncnt = 0;
  }
  __syncthreads();
  if (last && threadIdx.x < 64){
    float ss = 0.f, qq = 0.f;
    #pragma unroll 8
    for (int b = 0; b < 128; b++){
      ss += __ldcg(&g_part[b*128 + c]);
      qq += __ldcg(&g_part[b*128 + 64 + c]);
    }
    const float inv = 1.f/(float)NN;
    float mean = ss*inv;
    float var  = qq*inv - mean*mean;
    float rstd = rsqrtf(var + 1e-5f);
    float scv = rstd*gam[c];
    g_bnscale[c] = scv;
    g_bnshift[c] = bet[c] - mean*scv;
  }
}

// ---------------- final MLP (applies BN3 at load) ----------------------------
__global__ void __launch_bounds__(256) k_mlp1(const float* __restrict__ x,
                                              const float* __restrict__ W,
                                              const float* __restrict__ b){
  int j = threadIdx.x & 63, g = threadIdx.x >> 6;
  float wreg[69];
  #pragma unroll
  for (int k = 0; k < 69; k++) wreg[k] = W[k*64 + j];
  float bj = b[j];
  float4 sc4, sh4;
  if (j < 16){
    sc4 = ((const float4*)g_bnscale)[j];
    sh4 = ((const float4*)g_bnshift)[j];
  }
  __shared__ __align__(16) float sh[4][72];
  for (int n0 = blockIdx.x*4; n0 < NN; n0 += gridDim.x*4){
    int n = n0 + g;
    if (n < NN){
      if (j < 16){
        float4 v = ((const float4*)(g_buf64 + (size_t)n*64))[j];
        v.x = fmaxf(v.x*sc4.x + sh4.x, 0.f);
        v.y = fmaxf(v.y*sc4.y + sh4.y, 0.f);
        v.z = fmaxf(v.z*sc4.z + sh4.z, 0.f);
        v.w = fmaxf(v.w*sc4.w + sh4.w, 0.f);
        ((float4*)sh[g])[j] = v;
      }
      if (j >= 16 && j < 21) sh[g][48 + j] = x[(size_t)n*16 + (j - 7)];  // ctx = x[:,9:14]
    }
    __syncthreads();
    if (n < NN){
      float acc = bj;
      #pragma unroll
      for (int k = 0; k < 17; k++){
        float4 h4 = ((float4*)sh[g])[k];
        acc += h4.x*wreg[4*k] + h4.y*wreg[4*k+1] + h4.z*wreg[4*k+2] + h4.w*wreg[4*k+3];
      }
      acc += sh[g][68]*wreg[68];
      g_h128[(size_t)n*64 + j] = fmaxf(acc, 0.f);   // reuse g_h128 as hidden buffer
    }
    __syncthreads();
  }
}

__global__ void __launch_bounds__(256) k_mlp2(const float* __restrict__ W2,
                                              const float* __restrict__ b2,
                                              const float* __restrict__ pW,
                                              const float* __restrict__ pb,
                                              const float* __restrict__ vW,
                                              const float* __restrict__ vb,
                                              float* __restrict__ out){
  int j = threadIdx.x & 63, g = threadIdx.x >> 6, tid = threadIdx.x;
  float wreg[64];
  #pragma unroll
  for (int k = 0; k < 64; k++) wreg[k] = W2[k*64 + j];
  float b2j = b2[j], pwj = pW[j], vwj = vW[j];
  float pb0 = pb[0], vb0 = vb[0];
  __shared__ __align__(16) float st[4][64];
  __shared__ float rl[256], rv[256];
  for (int n0 = blockIdx.x*4; n0 < NN; n0 += gridDim.x*4){
    int n = n0 + g;
    if (n < NN && j < 16)
      ((float4*)st[g])[j] = ((const float4*)(g_h128 + (size_t)n*64))[j];
    __syncthreads();
    float u = b2j;
    #pragma unroll
    for (int k = 0; k < 16; k++){
      float4 t4 = ((float4*)st[g])[k];
      u += t4.x*wreg[4*k] + t4.y*wreg[4*k+1] + t4.z*wreg[4*k+2] + t4.w*wreg[4*k+3];
    }
    rl[tid] = (n < NN) ? u*pwj : 0.f;
    rv[tid] = (n < NN) ? u*vwj : 0.f;
    __syncthreads();
    #pragma unroll
    for (int s = 32; s >= 1; s >>= 1){
      if (j < s){ rl[tid] += rl[tid+s]; rv[tid] += rv[tid+s]; }
      __syncthreads();
    }
    if (j == 0 && n < NN){
      out[n]      = rl[tid] + pb0;
      out[NN + n] = rv[tid] + vb0;
    }
    __syncthreads();
  }
}

// ---------------- launch -----------------------------------------------------
extern "C" void kernel_launch(void* const* d_in, const int* in_sizes, int n_in,
                              void* d_out, int out_size){
  const float* x   = (const float*)d_in[0];
  const int*   ei  = (const int*)  d_in[1];
  const float* W1  = (const float*)d_in[2];
  const float* as1 = (const float*)d_in[3];
  const float* ad1 = (const float*)d_in[4];
  const float* b1  = (const float*)d_in[5];
  const float* g1  = (const float*)d_in[6];
  const float* be1 = (const float*)d_in[7];
  const float* W2  = (const float*)d_in[8];
  const float* as2 = (const float*)d_in[9];
  const float* ad2 = (const float*)d_in[10];
  const float* b2  = (const float*)d_in[11];
  const float* g2  = (const float*)d_in[12];
  const float* be2 = (const float*)d_in[13];
  const float* W3  = (const float*)d_in[14];
  const float* as3 = (const float*)d_in[15];
  const float* ad3 = (const float*)d_in[16];
  const float* b3  = (const float*)d_in[17];
  const float* g3  = (const float*)d_in[18];
  const float* be3 = (const float*)d_in[19];
  const float* mW1 = (const float*)d_in[20];
  const float* mb1 = (const float*)d_in[21];
  const float* mW2 = (const float*)d_in[22];
  const float* mb2 = (const float*)d_in[23];
  const float* pW  = (const float*)d_in[24];
  const float* pb  = (const float*)d_in[25];
  const float* vW  = (const float*)d_in[26];
  const float* vb  = (const float*)d_in[27];
  float* out = (float*)d_out;

  const int TB = 256;
  const int gE    = (EE + TB - 1)/TB;
  const int gWarp = (NN*32 + TB - 1)/TB;   // warp-per-node kernels
  const int gGemm = 1184;                  // 8 * 148 SMs

  // CSR build (g_deg zeroed at module load / by previous k_scatter)
  k_count<<<gE, TB>>>(ei);
  k_scan1<<<NB1, TB>>>();
  k_scan23c<<<NB1, TB>>>();
  k_scatter<<<gE, TB>>>(ei);

  // layer 1
  k_gemm<16,false><<<gGemm, TB>>>(x, W1, as1, ad1);
  k_aggregate<<<gWarp, TB>>>(b1);
  k_bnstatsfinal<<<128, TB>>>(g1, be1);

  // layer 2
  k_gemm<64,true><<<gGemm, TB>>>(nullptr, W2, as2, ad2);
  k_aggregate<<<gWarp, TB>>>(b2);
  k_bnstatsfinal<<<128, TB>>>(g2, be2);

  // layer 3
  k_gemm<64,true><<<gGemm, TB>>>(nullptr, W3, as3, ad3);
  k_aggregate<<<gWarp, TB>>>(b3);
  k_bnstatsfinal<<<128, TB>>>(g3, be3);

  // MLP + heads
  k_mlp1<<<gGemm, TB>>>(x, mW1, mb1);
  k_mlp2<<<gGemm, TB>>>(mW2, mb2, pW, pb, vW, vb, out);
}

// round 4
// speedup vs baseline: 1.0423x; 1.0423x over previous
#include <cuda_runtime.h>
#include <math.h>

#define NN 100000
#define EE 1000000
#define NB1 98     // ceil(NN/1024)
#define GOUT 256   // grid for k_out (matches g_part rows)

// ---------------- scratch (static device globals; no allocation) -------------
__device__ float g_x64[(size_t)NN*64];     // post-BN relu'd features (layers 2,3)
__device__ float g_z[(size_t)NN*128];      // aggregated per-head features / MLP hidden
__device__ float g_buf64[(size_t)NN*64];   // layer output (pre-BN)
__device__ float g_as[NN*2];
__device__ float g_ad[NN*2];
__device__ int   g_deg[NN];                // zero-init at load; re-zeroed by k_scatter
__device__ int   g_off[NN];
__device__ int   g_cursor[NN];
__device__ int   g_esrc[EE];
__device__ int   g_bsum[128];
__device__ float g_part[GOUT*128];         // BN partials per k_out block
__device__ float g_bnscale[64];
__device__ float g_bnshift[64];
__device__ int   g_bncnt;

__device__ __forceinline__ float lrelu(float v){ return v > 0.f ? v : 0.2f*v; }

// ---------------- CSR build --------------------------------------------------
__global__ void k_count(const int* __restrict__ ei){
  int e = blockIdx.x*blockDim.x + threadIdx.x;
  if (e < EE) atomicAdd(&g_deg[ei[EE + e]], 1);
}

__global__ void k_scan1(){
  __shared__ int s[256];
  int tid = threadIdx.x;
  int base = blockIdx.x*1024 + tid*4;
  int v[4]; int loc = 0;
  #pragma unroll
  for (int i = 0; i < 4; i++){ int idx = base + i; v[i] = (idx < NN) ? g_deg[idx] : 0; loc += v[i]; }
  s[tid] = loc; __syncthreads();
  #pragma unroll
  for (int d = 1; d < 256; d <<= 1){
    int t = (tid >= d) ? s[tid-d] : 0; __syncthreads();
    s[tid] += t; __syncthreads();
  }
  int run = (tid == 0) ? 0 : s[tid-1];
  #pragma unroll
  for (int i = 0; i < 4; i++){ run += v[i]; int idx = base + i; if (idx < NN) g_off[idx] = run; }
  if (tid == 255) g_bsum[blockIdx.x] = s[255];
}

__global__ void k_scan23c(){
  int tid = threadIdx.x;
  int b = blockIdx.x;
  __shared__ int swarp[8];
  int v = (tid < b) ? g_bsum[tid] : 0;     // b <= 97 < 128
  #pragma unroll
  for (int o = 16; o; o >>= 1) v += __shfl_xor_sync(0xffffffffu, v, o);
  if ((tid & 31) == 0) swarp[tid >> 5] = v;
  __syncthreads();
  int pre = swarp[0] + swarp[1] + swarp[2] + swarp[3];
  int base = b*1024 + tid*4;
  #pragma unroll
  for (int i = 0; i < 4; i++){
    int idx = base + i;
    if (idx < NN){
      int off = g_off[idx] + pre;
      g_off[idx] = off;
      g_cursor[idx] = off - g_deg[idx];
    }
  }
}

__global__ void k_scatter(const int* __restrict__ ei){
  int e = blockIdx.x*blockDim.x + threadIdx.x;
  if (e < EE){
    int s = ei[e], d = ei[EE + e];
    int pos = atomicAdd(&g_cursor[d], 1);
    g_esrc[pos] = s;
  }
  if (e < NN) g_deg[e] = 0;   // re-zero for next replay (deg is dead by now)
}

// ---------------- attention scores (layers 2,3): BN+relu + a_s/a_d ----------
// wa_h[k] = sum_c W[k, h*64+c]*as[h,c]; a_s[n,h] = x'_n . wa_h  (x' = relu(bn(prev)))
__global__ void __launch_bounds__(256) k_att(const float* __restrict__ W,
                                             const float* __restrict__ as_,
                                             const float* __restrict__ ad_){
  __shared__ float swa[2][64], swd[2][64];
  int tid = threadIdx.x;
  {
    int h = (tid >> 6) & 1;
    int k = tid & 63;
    const float* att = (tid < 128) ? as_ : ad_;
    const float* wrow = W + k*128 + h*64;
    float acc = 0.f;
    #pragma unroll 16
    for (int c = 0; c < 64; c++) acc += wrow[c]*att[h*64 + c];
    if (tid < 128) swa[h][k] = acc; else swd[h][k] = acc;
  }
  int lane = tid & 31, w = tid >> 5;
  float2 sc2 = ((const float2*)g_bnscale)[lane];
  float2 sh2 = ((const float2*)g_bnshift)[lane];
  __syncthreads();
  int k0 = 2*lane;
  float wa0a = swa[0][k0], wa0b = swa[0][k0+1];
  float wa1a = swa[1][k0], wa1b = swa[1][k0+1];
  float wd0a = swd[0][k0], wd0b = swd[0][k0+1];
  float wd1a = swd[1][k0], wd1b = swd[1][k0+1];
  for (int n = blockIdx.x*8 + w; n < NN; n += gridDim.x*8){
    float2 v = ((const float2*)(g_buf64 + (size_t)n*64))[lane];
    v.x = fmaxf(v.x*sc2.x + sh2.x, 0.f);
    v.y = fmaxf(v.y*sc2.y + sh2.y, 0.f);
    ((float2*)(g_x64 + (size_t)n*64))[lane] = v;
    float s0 = v.x*wa0a + v.y*wa0b;
    float s1 = v.x*wa1a + v.y*wa1b;
    float d0 = v.x*wd0a + v.y*wd0b;
    float d1 = v.x*wd1a + v.y*wd1b;
    #pragma unroll
    for (int o = 16; o; o >>= 1){
      s0 += __shfl_xor_sync(0xffffffffu, s0, o);
      s1 += __shfl_xor_sync(0xffffffffu, s1, o);
      d0 += __shfl_xor_sync(0xffffffffu, d0, o);
      d1 += __shfl_xor_sync(0xffffffffu, d1, o);
    }
    if (lane == 0){
      g_as[2*n] = s0; g_as[2*n+1] = s1;
      g_ad[2*n] = d0; g_ad[2*n+1] = d1;
    }
  }
}

// ---------------- attention scores (layer 1): raw 16-dim x -------------------
__global__ void __launch_bounds__(256) k_att1(const float* __restrict__ x,
                                              const float* __restrict__ W,
                                              const float* __restrict__ as_,
                                              const float* __restrict__ ad_){
  __shared__ float swa[2][16], swd[2][16];
  int tid = threadIdx.x;
  if (tid < 64){
    int h = (tid >> 4) & 1;
    int k = tid & 15;
    const float* att = (tid < 32) ? as_ : ad_;
    const float* wrow = W + k*128 + h*64;
    float acc = 0.f;
    #pragma unroll 16
    for (int c = 0; c < 64; c++) acc += wrow[c]*att[h*64 + c];
    if (tid < 32) swa[h][k] = acc; else swd[h][k] = acc;
  }
  __syncthreads();
  int lane = tid & 31, w = tid >> 5;
  int k0 = 2*lane;
  bool act = (k0 < 16);
  float wa0a=0,wa0b=0,wa1a=0,wa1b=0,wd0a=0,wd0b=0,wd1a=0,wd1b=0;
  if (act){
    wa0a = swa[0][k0]; wa0b = swa[0][k0+1];
    wa1a = swa[1][k0]; wa1b = swa[1][k0+1];
    wd0a = swd[0][k0]; wd0b = swd[0][k0+1];
    wd1a = swd[1][k0]; wd1b = swd[1][k0+1];
  }
  for (int n = blockIdx.x*8 + w; n < NN; n += gridDim.x*8){
    float2 v = make_float2(0.f, 0.f);
    if (act) v = ((const float2*)(x + (size_t)n*16))[lane];
    float s0 = v.x*wa0a + v.y*wa0b;
    float s1 = v.x*wa1a + v.y*wa1b;
    float d0 = v.x*wd0a + v.y*wd0b;
    float d1 = v.x*wd1a + v.y*wd1b;
    #pragma unroll
    for (int o = 16; o; o >>= 1){
      s0 += __shfl_xor_sync(0xffffffffu, s0, o);
      s1 += __shfl_xor_sync(0xffffffffu, s1, o);
      d0 += __shfl_xor_sync(0xffffffffu, d0, o);
      d1 += __shfl_xor_sync(0xffffffffu, d1, o);
    }
    if (lane == 0){
      g_as[2*n] = s0; g_as[2*n+1] = s1;
      g_ad[2*n] = d0; g_ad[2*n+1] = d1;
    }
  }
}

// ---------------- GAT aggregation on RAW features: y_h = sum alpha_h x_s -----
// One warp per dst node; lane holds channels [2*lane, 2*lane+1].
// Writes normalized y to g_z[n*2D + h*D + k].
template<int D, bool L1>
__global__ void __launch_bounds__(256) k_aggregate(const float* __restrict__ xin){
  const float* xsrc = L1 ? xin : (const float*)g_x64;
  int t = blockIdx.x*blockDim.x + threadIdx.x;
  int n = t >> 5, lane = t & 31;
  if (n >= NN) return;
  int k0 = 2*lane;
  bool act = (k0 < D);
  int start = n ? g_off[n-1] : 0;
  int end   = g_off[n];
  int len   = end - start;
  float ad0 = g_ad[2*n], ad1 = g_ad[2*n+1];
  float es0 = lrelu(g_as[2*n]   + ad0);   // self loop
  float es1 = lrelu(g_as[2*n+1] + ad1);
  float2 vself = make_float2(0.f, 0.f);
  if (act) vself = ((const float2*)(xsrc + (size_t)n*D))[lane];

  float2 y0, y1;
  float den0, den1;

  if (len <= 32){
    int s = 0; float e0 = -1e30f, e1 = -1e30f;
    if (lane < len){
      s = g_esrc[start + lane];
      float2 asv = ((const float2*)g_as)[s];
      e0 = lrelu(asv.x + ad0);
      e1 = lrelu(asv.y + ad1);
    }
    float m0 = fmaxf(e0, es0), m1 = fmaxf(e1, es1);
    #pragma unroll
    for (int o = 16; o; o >>= 1){
      m0 = fmaxf(m0, __shfl_xor_sync(0xffffffffu, m0, o));
      m1 = fmaxf(m1, __shfl_xor_sync(0xffffffffu, m1, o));
    }
    float w0 = (lane < len) ? __expf(e0 - m0) : 0.f;
    float w1 = (lane < len) ? __expf(e1 - m1) : 0.f;
    float d0 = w0, d1 = w1;
    #pragma unroll
    for (int o = 16; o; o >>= 1){
      d0 += __shfl_xor_sync(0xffffffffu, d0, o);
      d1 += __shfl_xor_sync(0xffffffffu, d1, o);
    }
    float ws0 = __expf(es0 - m0), ws1 = __expf(es1 - m1);
    den0 = d0 + ws0 + 1e-16f;
    den1 = d1 + ws1 + 1e-16f;
    y0.x = ws0*vself.x; y0.y = ws0*vself.y;
    y1.x = ws1*vself.x; y1.y = ws1*vself.y;
    #pragma unroll 4
    for (int k = 0; k < len; k++){
      int   sk  = __shfl_sync(0xffffffffu, s,  k);
      float wk0 = __shfl_sync(0xffffffffu, w0, k);
      float wk1 = __shfl_sync(0xffffffffu, w1, k);
      float2 v = make_float2(0.f, 0.f);
      if (act) v = ((const float2*)(xsrc + (size_t)sk*D))[lane];
      y0.x += wk0*v.x; y0.y += wk0*v.y;
      y1.x += wk1*v.x; y1.y += wk1*v.y;
    }
  } else {
    // rare high-degree path: two passes, chunked
    float m0 = es0, m1 = es1;
    for (int i = start + lane; i < end; i += 32){
      int s = g_esrc[i];
      float2 asv = ((const float2*)g_as)[s];
      m0 = fmaxf(m0, lrelu(asv.x + ad0));
      m1 = fmaxf(m1, lrelu(asv.y + ad1));
    }
    #pragma unroll
    for (int o = 16; o; o >>= 1){
      m0 = fmaxf(m0, __shfl_xor_sync(0xffffffffu, m0, o));
      m1 = fmaxf(m1, __shfl_xor_sync(0xffffffffu, m1, o));
    }
    float ws0 = __expf(es0 - m0), ws1 = __expf(es1 - m1);
    y0.x = ws0*vself.x; y0.y = ws0*vself.y;
    y1.x = ws1*vself.x; y1.y = ws1*vself.y;
    float d0 = 0.f, d1 = 0.f;
    for (int base = start; base < end; base += 32){
      int cnt = min(32, end - base);
      int s = 0; float w0 = 0.f, w1 = 0.f;
      if (lane < cnt){
        s = g_esrc[base + lane];
        float2 asv = ((const float2*)g_as)[s];
        w0 = __expf(lrelu(asv.x + ad0) - m0);
        w1 = __expf(lrelu(asv.y + ad1) - m1);
      }
      d0 += w0; d1 += w1;
      for (int k = 0; k < cnt; k++){
        int   sk  = __shfl_sync(0xffffffffu, s,  k);
        float wk0 = __shfl_sync(0xffffffffu, w0, k);
        float wk1 = __shfl_sync(0xffffffffu, w1, k);
        float2 v = make_float2(0.f, 0.f);
        if (act) v = ((const float2*)(xsrc + (size_t)sk*D))[lane];
        y0.x += wk0*v.x; y0.y += wk0*v.y;
        y1.x += wk1*v.x; y1.y += wk1*v.y;
      }
    }
    #pragma unroll
    for (int o = 16; o; o >>= 1){
      d0 += __shfl_xor_sync(0xffffffffu, d0, o);
      d1 += __shfl_xor_sync(0xffffffffu, d1, o);
    }
    den0 = d0 + ws0 + 1e-16f;
    den1 = d1 + ws1 + 1e-16f;
  }

  if (act){
    float i0 = 1.f/den0, i1 = 1.f/den1;
    float* zr = g_z + (size_t)n*(2*D);
    ((float2*)(zr))[lane]        = make_float2(y0.x*i0, y0.y*i0);
    ((float2*)(zr + D))[lane]    = make_float2(y1.x*i1, y1.y*i1);
  }
}

// ---------------- output transform: out = 0.5*(y0@W_h0 + y1@W_h1) + b --------
// + fused BN partial stats with last-block finalize -> g_bnscale/g_bnshift.
template<int D>
__global__ void __launch_bounds__(256) k_out(const float* __restrict__ W,
                                             const float* __restrict__ b,
                                             const float* __restrict__ gam,
                                             const float* __restrict__ bet){
  int tid = threadIdx.x;
  int j  = tid & 63;
  int hb = (tid >> 6) & 1;
  int g  = tid >> 7;
  float wreg[D];
  #pragma unroll
  for (int k = 0; k < D; k++) wreg[k] = W[k*128 + hb*64 + j];
  float bj = b[j];
  __shared__ __align__(16) float sy[2][2*D];
  __shared__ float sacc[256];
  float bs = 0.f, bq = 0.f;
  for (int n0 = blockIdx.x*2; n0 < NN; n0 += gridDim.x*2){
    int n = n0 + g;
    int t2 = tid & 127;
    if (n < NN && t2 < D)
      ((float2*)sy[g])[t2] = ((const float2*)(g_z + (size_t)n*(2*D)))[t2];
    __syncthreads();
    float acc = 0.f;
    if (n < NN){
      #pragma unroll
      for (int k4 = 0; k4 < D/4; k4++){
        float4 y4 = ((float4*)sy[g])[hb*(D/4) + k4];
        acc += y4.x*wreg[4*k4] + y4.y*wreg[4*k4+1] + y4.z*wreg[4*k4+2] + y4.w*wreg[4*k4+3];
      }
    }
    sacc[tid] = acc;
    __syncthreads();
    if (hb == 0 && n < NN){
      float r = 0.5f*(sacc[tid] + sacc[tid+64]) + bj;
      g_buf64[(size_t)n*64 + j] = r;
      bs += r; bq += r*r;
    }
    __syncthreads();
  }
  sacc[tid] = bs;
  __syncthreads();
  float tbs = (tid < 64) ? (sacc[tid] + sacc[tid+128]) : 0.f;
  __syncthreads();
  sacc[tid] = bq;
  __syncthreads();
  if (tid < 64){
    g_part[blockIdx.x*128 + tid]      = tbs;
    g_part[blockIdx.x*128 + 64 + tid] = sacc[tid] + sacc[tid+128];
  }
  __threadfence();
  __shared__ bool lastb;
  if (tid == 0){
    lastb = (atomicAdd(&g_bncnt, 1) == GOUT-1);
    if (lastb) g_bncnt = 0;
  }
  __syncthreads();
  if (lastb && tid < 64){
    float ss = 0.f, qq = 0.f;
    #pragma unroll 8
    for (int bb = 0; bb < GOUT; bb++){
      ss += __ldcg(&g_part[bb*128 + tid]);
      qq += __ldcg(&g_part[bb*128 + 64 + tid]);
    }
    const float inv = 1.f/(float)NN;
    float mean = ss*inv;
    float var  = qq*inv - mean*mean;
    float rstd = rsqrtf(var + 1e-5f);
    float scv = rstd*gam[tid];
    g_bnscale[tid] = scv;
    g_bnshift[tid] = bet[tid] - mean*scv;
  }
}

// ---------------- final MLP (applies BN3 at load) ----------------------------
__global__ void __launch_bounds__(256) k_mlp1(const float* __restrict__ x,
                                              const float* __restrict__ W,
                                              const float* __restrict__ b){
  int j = threadIdx.x & 63, g = threadIdx.x >> 6;
  float wreg[69];
  #pragma unroll
  for (int k = 0; k < 69; k++) wreg[k] = W[k*64 + j];
  float bj = b[j];
  float4 sc4, sh4;
  if (j < 16){
    sc4 = ((const float4*)g_bnscale)[j];
    sh4 = ((const float4*)g_bnshift)[j];
  }
  __shared__ __align__(16) float sh[4][72];
  for (int n0 = blockIdx.x*4; n0 < NN; n0 += gridDim.x*4){
    int n = n0 + g;
    if (n < NN){
      if (j < 16){
        float4 v = ((const float4*)(g_buf64 + (size_t)n*64))[j];
        v.x = fmaxf(v.x*sc4.x + sh4.x, 0.f);
        v.y = fmaxf(v.y*sc4.y + sh4.y, 0.f);
        v.z = fmaxf(v.z*sc4.z + sh4.z, 0.f);
        v.w = fmaxf(v.w*sc4.w + sh4.w, 0.f);
        ((float4*)sh[g])[j] = v;
      }
      if (j >= 16 && j < 21) sh[g][48 + j] = x[(size_t)n*16 + (j - 7)];  // ctx = x[:,9:14]
    }
    __syncthreads();
    if (n < NN){
      float acc = bj;
      #pragma unroll
      for (int k = 0; k < 17; k++){
        float4 h4 = ((float4*)sh[g])[k];
        acc += h4.x*wreg[4*k] + h4.y*wreg[4*k+1] + h4.z*wreg[4*k+2] + h4.w*wreg[4*k+3];
      }
      acc += sh[g][68]*wreg[68];
      g_z[(size_t)n*64 + j] = fmaxf(acc, 0.f);   // hidden buffer
    }
    __syncthreads();
  }
}

__global__ void __launch_bounds__(256) k_mlp2(const float* __restrict__ W2,
                                              const float* __restrict__ b2,
                                              const float* __restrict__ pW,
                                              const float* __restrict__ pb,
                                              const float* __restrict__ vW,
                                              const float* __restrict__ vb,
                                              float* __restrict__ out){
  int j = threadIdx.x & 63, g = threadIdx.x >> 6, tid = threadIdx.x;
  float wreg[64];
  #pragma unroll
  for (int k = 0; k < 64; k++) wreg[k] = W2[k*64 + j];
  float b2j = b2[j], pwj = pW[j], vwj = vW[j];
  float pb0 = pb[0], vb0 = vb[0];
  __shared__ __align__(16) float st[4][64];
  __shared__ float rl[256], rv[256];
  for (int n0 = blockIdx.x*4; n0 < NN; n0 += gridDim.x*4){
    int n = n0 + g;
    if (n < NN && j < 16)
      ((float4*)st[g])[j] = ((const float4*)(g_z + (size_t)n*64))[j];
    __syncthreads();
    float u = b2j;
    #pragma unroll
    for (int k = 0; k < 16; k++){
      float4 t4 = ((float4*)st[g])[k];
      u += t4.x*wreg[4*k] + t4.y*wreg[4*k+1] + t4.z*wreg[4*k+2] + t4.w*wreg[4*k+3];
    }
    rl[tid] = (n < NN) ? u*pwj : 0.f;
    rv[tid] = (n < NN) ? u*vwj : 0.f;
    __syncthreads();
    #pragma unroll
    for (int s = 32; s >= 1; s >>= 1){
      if (j < s){ rl[tid] += rl[tid+s]; rv[tid] += rv[tid+s]; }
      __syncthreads();
    }
    if (j == 0 && n < NN){
      out[n]      = rl[tid] + pb0;
      out[NN + n] = rv[tid] + vb0;
    }
    __syncthreads();
  }
}

// ---------------- launch -----------------------------------------------------
extern "C" void kernel_launch(void* const* d_in, const int* in_sizes, int n_in,
                              void* d_out, int out_size){
  const float* x   = (const float*)d_in[0];
  const int*   ei  = (const int*)  d_in[1];
  const float* W1  = (const float*)d_in[2];
  const float* as1 = (const float*)d_in[3];
  const float* ad1 = (const float*)d_in[4];
  const float* b1  = (const float*)d_in[5];
  const float* g1  = (const float*)d_in[6];
  const float* be1 = (const float*)d_in[7];
  const float* W2  = (const float*)d_in[8];
  const float* as2 = (const float*)d_in[9];
  const float* ad2 = (const float*)d_in[10];
  const float* b2  = (const float*)d_in[11];
  const float* g2  = (const float*)d_in[12];
  const float* be2 = (const float*)d_in[13];
  const float* W3  = (const float*)d_in[14];
  const float* as3 = (const float*)d_in[15];
  const float* ad3 = (const float*)d_in[16];
  const float* b3  = (const float*)d_in[17];
  const float* g3  = (const float*)d_in[18];
  const float* be3 = (const float*)d_in[19];
  const float* mW1 = (const float*)d_in[20];
  const float* mb1 = (const float*)d_in[21];
  const float* mW2 = (const float*)d_in[22];
  const float* mb2 = (const float*)d_in[23];
  const float* pW  = (const float*)d_in[24];
  const float* pb  = (const float*)d_in[25];
  const float* vW  = (const float*)d_in[26];
  const float* vb  = (const float*)d_in[27];
  float* out = (float*)d_out;

  const int TB = 256;
  const int gE    = (EE + TB - 1)/TB;
  const int gWarp = (NN*32 + TB - 1)/TB;   // warp-per-node kernels
  const int gAtt  = 592;                   // 4 * 148 SMs
  const int gMlp  = 1184;

  // CSR build (g_deg zeroed at module load / by previous k_scatter)
  k_count<<<gE, TB>>>(ei);
  k_scan1<<<NB1, TB>>>();
  k_scan23c<<<NB1, TB>>>();
  k_scatter<<<gE, TB>>>(ei);

  // layer 1 (D=16, raw x)
  k_att1<<<gAtt, TB>>>(x, W1, as1, ad1);
  k_aggregate<16,true><<<gWarp, TB>>>(x);
  k_out<16><<<GOUT, TB>>>(W1, b1, g1, be1);

  // layer 2 (D=64)
  k_att<<<gAtt, TB>>>(W2, as2, ad2);
  k_aggregate<64,false><<<gWarp, TB>>>(nullptr);
  k_out<64><<<GOUT, TB>>>(W2, b2, g2, be2);

  // layer 3 (D=64)
  k_att<<<gAtt, TB>>>(W3, as3, ad3);
  k_aggregate<64,false><<<gWarp, TB>>>(nullptr);
  k_out<64><<<GOUT, TB>>>(W3, b3, g3, be3);

  // MLP + heads
  k_mlp1<<<gMlp, TB>>>(x, mW1, mb1);
  k_mlp2<<<gMlp, TB>>>(mW2, mb2, pW, pb, vW, vb, out);
}

// round 5
// speedup vs baseline: 1.0744x; 1.0308x over previous
#include <cuda_runtime.h>
#include <math.h>

#define NN 100000
#define EE 1000000
#define NB1 98     // ceil(NN/1024)
#define GOUT 256   // grid for k_out (matches g_part rows)

typedef unsigned long long ull;

// ---------------- scratch (static device globals; no allocation) -------------
__device__ float g_x64[(size_t)NN*64];     // post-BN relu'd features (layers 2,3)
__device__ float g_z[(size_t)NN*128];      // aggregated per-head features / MLP hidden
__device__ float g_buf64[(size_t)NN*64];   // layer output (pre-BN)
__device__ float g_as[NN*2];
__device__ float g_ad[NN*2];
__device__ int   g_deg[NN];                // zero-init at load; re-zeroed by k_scatter
__device__ int   g_off[NN];
__device__ int   g_cursor[NN];
__device__ int   g_esrc[EE];
__device__ int   g_bsum[128];
__device__ float g_part[GOUT*128];         // BN partials per k_out block
__device__ float g_bnscale[64];
__device__ float g_bnshift[64];
__device__ int   g_bncnt;

__device__ __forceinline__ float lrelu(float v){ return v > 0.f ? v : 0.2f*v; }

__device__ __forceinline__ ull pk2(float lo, float hi){
  ull u; asm("mov.b64 %0, {%1, %2};" : "=l"(u) : "f"(lo), "f"(hi)); return u;
}
__device__ __forceinline__ void upk2(float& lo, float& hi, ull u){
  asm("mov.b64 {%0, %1}, %2;" : "=f"(lo), "=f"(hi) : "l"(u));
}
#define FMA2(d, a, b, c) \
  asm("fma.rn.f32x2 %0, %1, %2, %3;" : "=l"(d) : "l"(a), "l"(b), "l"(c))

// ---------------- CSR build --------------------------------------------------
__global__ void k_count(const int* __restrict__ ei){
  int e = blockIdx.x*blockDim.x + threadIdx.x;
  if (e < EE) atomicAdd(&g_deg[ei[EE + e]], 1);
}

__global__ void k_scan1(){
  __shared__ int s[256];
  int tid = threadIdx.x;
  int base = blockIdx.x*1024 + tid*4;
  int v[4]; int loc = 0;
  #pragma unroll
  for (int i = 0; i < 4; i++){ int idx = base + i; v[i] = (idx < NN) ? g_deg[idx] : 0; loc += v[i]; }
  s[tid] = loc; __syncthreads();
  #pragma unroll
  for (int d = 1; d < 256; d <<= 1){
    int t = (tid >= d) ? s[tid-d] : 0; __syncthreads();
    s[tid] += t; __syncthreads();
  }
  int run = (tid == 0) ? 0 : s[tid-1];
  #pragma unroll
  for (int i = 0; i < 4; i++){ run += v[i]; int idx = base + i; if (idx < NN) g_off[idx] = run; }
  if (tid == 255) g_bsum[blockIdx.x] = s[255];
}

__global__ void k_scan23c(){
  int tid = threadIdx.x;
  int b = blockIdx.x;
  __shared__ int swarp[8];
  int v = (tid < b) ? g_bsum[tid] : 0;     // b <= 97 < 128
  #pragma unroll
  for (int o = 16; o; o >>= 1) v += __shfl_xor_sync(0xffffffffu, v, o);
  if ((tid & 31) == 0) swarp[tid >> 5] = v;
  __syncthreads();
  int pre = swarp[0] + swarp[1] + swarp[2] + swarp[3];
  int base = b*1024 + tid*4;
  #pragma unroll
  for (int i = 0; i < 4; i++){
    int idx = base + i;
    if (idx < NN){
      int off = g_off[idx] + pre;
      g_off[idx] = off;
      g_cursor[idx] = off - g_deg[idx];
    }
  }
}

__global__ void k_scatter(const int* __restrict__ ei){
  int e = blockIdx.x*blockDim.x + threadIdx.x;
  if (e < EE){
    int s = ei[e], d = ei[EE + e];
    int pos = atomicAdd(&g_cursor[d], 1);
    g_esrc[pos] = s;
  }
  if (e < NN) g_deg[e] = 0;   // re-zero for next replay (deg is dead by now)
}

// ---------------- attention scores (layers 2,3): BN+relu + a_s/a_d ----------
__global__ void __launch_bounds__(256) k_att(const float* __restrict__ W,
                                             const float* __restrict__ as_,
                                             const float* __restrict__ ad_){
  __shared__ float swa[2][64], swd[2][64];
  int tid = threadIdx.x;
  {
    int h = (tid >> 6) & 1;
    int k = tid & 63;
    const float* att = (tid < 128) ? as_ : ad_;
    const float* wrow = W + k*128 + h*64;
    float acc = 0.f;
    #pragma unroll 16
    for (int c = 0; c < 64; c++) acc += wrow[c]*att[h*64 + c];
    if (tid < 128) swa[h][k] = acc; else swd[h][k] = acc;
  }
  int lane = tid & 31, w = tid >> 5;
  float2 sc2 = ((const float2*)g_bnscale)[lane];
  float2 sh2 = ((const float2*)g_bnshift)[lane];
  __syncthreads();
  int k0 = 2*lane;
  float wa0a = swa[0][k0], wa0b = swa[0][k0+1];
  float wa1a = swa[1][k0], wa1b = swa[1][k0+1];
  float wd0a = swd[0][k0], wd0b = swd[0][k0+1];
  float wd1a = swd[1][k0], wd1b = swd[1][k0+1];
  for (int n = blockIdx.x*8 + w; n < NN; n += gridDim.x*8){
    float2 v = ((const float2*)(g_buf64 + (size_t)n*64))[lane];
    v.x = fmaxf(v.x*sc2.x + sh2.x, 0.f);
    v.y = fmaxf(v.y*sc2.y + sh2.y, 0.f);
    ((float2*)(g_x64 + (size_t)n*64))[lane] = v;
    float s0 = v.x*wa0a + v.y*wa0b;
    float s1 = v.x*wa1a + v.y*wa1b;
    float d0 = v.x*wd0a + v.y*wd0b;
    float d1 = v.x*wd1a + v.y*wd1b;
    #pragma unroll
    for (int o = 16; o; o >>= 1){
      s0 += __shfl_xor_sync(0xffffffffu, s0, o);
      s1 += __shfl_xor_sync(0xffffffffu, s1, o);
      d0 += __shfl_xor_sync(0xffffffffu, d0, o);
      d1 += __shfl_xor_sync(0xffffffffu, d1, o);
    }
    if (lane == 0){
      g_as[2*n] = s0; g_as[2*n+1] = s1;
      g_ad[2*n] = d0; g_ad[2*n+1] = d1;
    }
  }
}

// ---------------- attention scores (layer 1): raw 16-dim x -------------------
__global__ void __launch_bounds__(256) k_att1(const float* __restrict__ x,
                                              const float* __restrict__ W,
                                              const float* __restrict__ as_,
                                              const float* __restrict__ ad_){
  __shared__ float swa[2][16], swd[2][16];
  int tid = threadIdx.x;
  if (tid < 64){
    int h = (tid >> 4) & 1;
    int k = tid & 15;
    const float* att = (tid < 32) ? as_ : ad_;
    const float* wrow = W + k*128 + h*64;
    float acc = 0.f;
    #pragma unroll 16
    for (int c = 0; c < 64; c++) acc += wrow[c]*att[h*64 + c];
    if (tid < 32) swa[h][k] = acc; else swd[h][k] = acc;
  }
  __syncthreads();
  int lane = tid & 31, w = tid >> 5;
  int k0 = 2*lane;
  bool act = (k0 < 16);
  float wa0a=0,wa0b=0,wa1a=0,wa1b=0,wd0a=0,wd0b=0,wd1a=0,wd1b=0;
  if (act){
    wa0a = swa[0][k0]; wa0b = swa[0][k0+1];
    wa1a = swa[1][k0]; wa1b = swa[1][k0+1];
    wd0a = swd[0][k0]; wd0b = swd[0][k0+1];
    wd1a = swd[1][k0]; wd1b = swd[1][k0+1];
  }
  for (int n = blockIdx.x*8 + w; n < NN; n += gridDim.x*8){
    float2 v = make_float2(0.f, 0.f);
    if (act) v = ((const float2*)(x + (size_t)n*16))[lane];
    float s0 = v.x*wa0a + v.y*wa0b;
    float s1 = v.x*wa1a + v.y*wa1b;
    float d0 = v.x*wd0a + v.y*wd0b;
    float d1 = v.x*wd1a + v.y*wd1b;
    #pragma unroll
    for (int o = 16; o; o >>= 1){
      s0 += __shfl_xor_sync(0xffffffffu, s0, o);
      s1 += __shfl_xor_sync(0xffffffffu, s1, o);
      d0 += __shfl_xor_sync(0xffffffffu, d0, o);
      d1 += __shfl_xor_sync(0xffffffffu, d1, o);
    }
    if (lane == 0){
      g_as[2*n] = s0; g_as[2*n+1] = s1;
      g_ad[2*n] = d0; g_ad[2*n+1] = d1;
    }
  }
}

// ---------------- GAT aggregation on RAW features ----------------------------
template<int D, bool L1>
__global__ void __launch_bounds__(256) k_aggregate(const float* __restrict__ xin){
  const float* xsrc = L1 ? xin : (const float*)g_x64;
  int t = blockIdx.x*blockDim.x + threadIdx.x;
  int n = t >> 5, lane = t & 31;
  if (n >= NN) return;
  int k0 = 2*lane;
  bool act = (k0 < D);
  int start = n ? g_off[n-1] : 0;
  int end   = g_off[n];
  int len   = end - start;
  float ad0 = g_ad[2*n], ad1 = g_ad[2*n+1];
  float es0 = lrelu(g_as[2*n]   + ad0);   // self loop
  float es1 = lrelu(g_as[2*n+1] + ad1);
  float2 vself = make_float2(0.f, 0.f);
  if (act) vself = ((const float2*)(xsrc + (size_t)n*D))[lane];

  float2 y0, y1;
  float den0, den1;

  if (len <= 32){
    int s = 0; float e0 = -1e30f, e1 = -1e30f;
    if (lane < len){
      s = g_esrc[start + lane];
      float2 asv = ((const float2*)g_as)[s];
      e0 = lrelu(asv.x + ad0);
      e1 = lrelu(asv.y + ad1);
    }
    float m0 = fmaxf(e0, es0), m1 = fmaxf(e1, es1);
    #pragma unroll
    for (int o = 16; o; o >>= 1){
      m0 = fmaxf(m0, __shfl_xor_sync(0xffffffffu, m0, o));
      m1 = fmaxf(m1, __shfl_xor_sync(0xffffffffu, m1, o));
    }
    float w0 = (lane < len) ? __expf(e0 - m0) : 0.f;
    float w1 = (lane < len) ? __expf(e1 - m1) : 0.f;
    float d0 = w0, d1 = w1;
    #pragma unroll
    for (int o = 16; o; o >>= 1){
      d0 += __shfl_xor_sync(0xffffffffu, d0, o);
      d1 += __shfl_xor_sync(0xffffffffu, d1, o);
    }
    float ws0 = __expf(es0 - m0), ws1 = __expf(es1 - m1);
    den0 = d0 + ws0 + 1e-16f;
    den1 = d1 + ws1 + 1e-16f;
    y0.x = ws0*vself.x; y0.y = ws0*vself.y;
    y1.x = ws1*vself.x; y1.y = ws1*vself.y;
    #pragma unroll 4
    for (int k = 0; k < len; k++){
      int   sk  = __shfl_sync(0xffffffffu, s,  k);
      float wk0 = __shfl_sync(0xffffffffu, w0, k);
      float wk1 = __shfl_sync(0xffffffffu, w1, k);
      float2 v = make_float2(0.f, 0.f);
      if (act) v = ((const float2*)(xsrc + (size_t)sk*D))[lane];
      y0.x += wk0*v.x; y0.y += wk0*v.y;
      y1.x += wk1*v.x; y1.y += wk1*v.y;
    }
  } else {
    float m0 = es0, m1 = es1;
    for (int i = start + lane; i < end; i += 32){
      int s = g_esrc[i];
      float2 asv = ((const float2*)g_as)[s];
      m0 = fmaxf(m0, lrelu(asv.x + ad0));
      m1 = fmaxf(m1, lrelu(asv.y + ad1));
    }
    #pragma unroll
    for (int o = 16; o; o >>= 1){
      m0 = fmaxf(m0, __shfl_xor_sync(0xffffffffu, m0, o));
      m1 = fmaxf(m1, __shfl_xor_sync(0xffffffffu, m1, o));
    }
    float ws0 = __expf(es0 - m0), ws1 = __expf(es1 - m1);
    y0.x = ws0*vself.x; y0.y = ws0*vself.y;
    y1.x = ws1*vself.x; y1.y = ws1*vself.y;
    float d0 = 0.f, d1 = 0.f;
    for (int base = start; base < end; base += 32){
      int cnt = min(32, end - base);
      int s = 0; float w0 = 0.f, w1 = 0.f;
      if (lane < cnt){
        s = g_esrc[base + lane];
        float2 asv = ((const float2*)g_as)[s];
        w0 = __expf(lrelu(asv.x + ad0) - m0);
        w1 = __expf(lrelu(asv.y + ad1) - m1);
      }
      d0 += w0; d1 += w1;
      for (int k = 0; k < cnt; k++){
        int   sk  = __shfl_sync(0xffffffffu, s,  k);
        float wk0 = __shfl_sync(0xffffffffu, w0, k);
        float wk1 = __shfl_sync(0xffffffffu, w1, k);
        float2 v = make_float2(0.f, 0.f);
        if (act) v = ((const float2*)(xsrc + (size_t)sk*D))[lane];
        y0.x += wk0*v.x; y0.y += wk0*v.y;
        y1.x += wk1*v.x; y1.y += wk1*v.y;
      }
    }
    #pragma unroll
    for (int o = 16; o; o >>= 1){
      d0 += __shfl_xor_sync(0xffffffffu, d0, o);
      d1 += __shfl_xor_sync(0xffffffffu, d1, o);
    }
    den0 = d0 + ws0 + 1e-16f;
    den1 = d1 + ws1 + 1e-16f;
  }

  if (act){
    float i0 = 1.f/den0, i1 = 1.f/den1;
    float* zr = g_z + (size_t)n*(2*D);
    ((float2*)(zr))[lane]        = make_float2(y0.x*i0, y0.y*i0);
    ((float2*)(zr + D))[lane]    = make_float2(y1.x*i1, y1.y*i1);
  }
}

// ---------------- output transform with packed f32x2 FMA ---------------------
// out = [y0,y1] @ (0.5*[W_h0; W_h1]) + b ; fused BN partials + last-block final.
template<int D>
__global__ void __launch_bounds__(256) k_out(const float* __restrict__ W,
                                             const float* __restrict__ b,
                                             const float* __restrict__ gam,
                                             const float* __restrict__ bet){
  int tid = threadIdx.x;
  int j  = tid & 63;
  int hb = (tid >> 6) & 1;
  int g  = tid >> 7;
  ull wp[D/2];
  #pragma unroll
  for (int k2 = 0; k2 < D/2; k2++)
    wp[k2] = pk2(0.5f*W[(2*k2)*128 + hb*64 + j], 0.5f*W[(2*k2+1)*128 + hb*64 + j]);
  float bj = b[j];
  __shared__ __align__(16) float sy[2][2*D];
  __shared__ float sacc[256];
  float bs = 0.f, bq = 0.f;
  for (int n0 = blockIdx.x*2; n0 < NN; n0 += gridDim.x*2){
    int n = n0 + g;
    int t2 = tid & 127;
    if (n < NN && t2 < D)
      ((float2*)sy[g])[t2] = ((const float2*)(g_z + (size_t)n*(2*D)))[t2];
    __syncthreads();
    float acc = 0.f;
    if (n < NN){
      ull acc2 = 0ull;
      const ull* yp = ((const ull*)sy[g]) + hb*(D/2);
      #pragma unroll
      for (int k2 = 0; k2 < D/2; k2++){
        FMA2(acc2, yp[k2], wp[k2], acc2);
      }
      float lo, hi; upk2(lo, hi, acc2);
      acc = lo + hi;
    }
    sacc[tid] = acc;
    __syncthreads();
    if (hb == 0 && n < NN){
      float r = sacc[tid] + sacc[tid+64] + bj;
      g_buf64[(size_t)n*64 + j] = r;
      bs += r; bq += r*r;
    }
    __syncthreads();
  }
  sacc[tid] = bs;
  __syncthreads();
  float tbs = (tid < 64) ? (sacc[tid] + sacc[tid+128]) : 0.f;
  __syncthreads();
  sacc[tid] = bq;
  __syncthreads();
  if (tid < 64){
    g_part[blockIdx.x*128 + tid]      = tbs;
    g_part[blockIdx.x*128 + 64 + tid] = sacc[tid] + sacc[tid+128];
  }
  __threadfence();
  __shared__ bool lastb;
  if (tid == 0){
    lastb = (atomicAdd(&g_bncnt, 1) == GOUT-1);
    if (lastb) g_bncnt = 0;
  }
  __syncthreads();
  if (lastb && tid < 64){
    float ss = 0.f, qq = 0.f;
    #pragma unroll 8
    for (int bb = 0; bb < GOUT; bb++){
      ss += __ldcg(&g_part[bb*128 + tid]);
      qq += __ldcg(&g_part[bb*128 + 64 + tid]);
    }
    const float inv = 1.f/(float)NN;
    float mean = ss*inv;
    float var  = qq*inv - mean*mean;
    float rstd = rsqrtf(var + 1e-5f);
    float scv = rstd*gam[tid];
    g_bnscale[tid] = scv;
    g_bnshift[tid] = bet[tid] - mean*scv;
  }
}

// ---------------- MLP layer 1 (BN3 at load, packed FMA) ----------------------
__global__ void __launch_bounds__(256) k_mlp1(const float* __restrict__ x,
                                              const float* __restrict__ W,
                                              const float* __restrict__ b){
  int j = threadIdx.x & 63, g = threadIdx.x >> 6;
  ull wp[34];
  #pragma unroll
  for (int k2 = 0; k2 < 34; k2++)
    wp[k2] = pk2(W[(2*k2)*64 + j], W[(2*k2+1)*64 + j]);
  float w68 = W[68*64 + j];
  float bj = b[j];
  float4 sc4, sh4;
  if (j < 16){
    sc4 = ((const float4*)g_bnscale)[j];
    sh4 = ((const float4*)g_bnshift)[j];
  }
  __shared__ __align__(16) float sh[4][72];
  for (int n0 = blockIdx.x*4; n0 < NN; n0 += gridDim.x*4){
    int n = n0 + g;
    if (n < NN){
      if (j < 16){
        float4 v = ((const float4*)(g_buf64 + (size_t)n*64))[j];
        v.x = fmaxf(v.x*sc4.x + sh4.x, 0.f);
        v.y = fmaxf(v.y*sc4.y + sh4.y, 0.f);
        v.z = fmaxf(v.z*sc4.z + sh4.z, 0.f);
        v.w = fmaxf(v.w*sc4.w + sh4.w, 0.f);
        ((float4*)sh[g])[j] = v;
      }
      if (j >= 16 && j < 21) sh[g][48 + j] = x[(size_t)n*16 + (j - 7)];  // ctx = x[:,9:14]
    }
    __syncthreads();
    if (n < NN){
      ull acc2 = 0ull;
      const ull* yp = (const ull*)sh[g];
      #pragma unroll
      for (int k2 = 0; k2 < 34; k2++){
        FMA2(acc2, yp[k2], wp[k2], acc2);
      }
      float lo, hi; upk2(lo, hi, acc2);
      float acc = lo + hi + sh[g][68]*w68 + bj;
      g_z[(size_t)n*64 + j] = fmaxf(acc, 0.f);   // hidden buffer
    }
    __syncthreads();
  }
}

// ---------------- heads: logits = t.q + cp ; value = t.v + cv ---------------
// q = mW2 @ pW (64), v = mW2 @ vW; collapsed since no relu after mW2.
__global__ void __launch_bounds__(256) k_heads(const float* __restrict__ W2,
                                               const float* __restrict__ b2,
                                               const float* __restrict__ pW,
                                               const float* __restrict__ pb,
                                               const float* __restrict__ vW,
                                               const float* __restrict__ vb,
                                               float* __restrict__ out){
  __shared__ float sq[64], sv[64];
  __shared__ float sc[2];
  int tid = threadIdx.x;
  if (tid < 128){
    int k = tid & 63;
    const float* hv = (tid < 64) ? pW : vW;
    const float* row = W2 + k*64;
    float acc = 0.f;
    #pragma unroll 16
    for (int c = 0; c < 64; c++) acc += row[c]*hv[c];
    if (tid < 64) sq[k] = acc; else sv[k] = acc;
  } else if (tid == 128){
    float a = 0.f, c = 0.f;
    #pragma unroll 16
    for (int jj = 0; jj < 64; jj++){ a += b2[jj]*pW[jj]; c += b2[jj]*vW[jj]; }
    sc[0] = a + pb[0];
    sc[1] = c + vb[0];
  }
  __syncthreads();
  int lane = tid & 31, w = tid >> 5;
  float2 q2 = ((const float2*)sq)[lane];
  float2 v2 = ((const float2*)sv)[lane];
  float cp = sc[0], cv = sc[1];
  for (int n = blockIdx.x*8 + w; n < NN; n += gridDim.x*8){
    float2 t2 = ((const float2*)(g_z + (size_t)n*64))[lane];
    float lp = t2.x*q2.x + t2.y*q2.y;
    float vp = t2.x*v2.x + t2.y*v2.y;
    #pragma unroll
    for (int o = 16; o; o >>= 1){
      lp += __shfl_xor_sync(0xffffffffu, lp, o);
      vp += __shfl_xor_sync(0xffffffffu, vp, o);
    }
    if (lane == 0){
      out[n]      = lp + cp;
      out[NN + n] = vp + cv;
    }
  }
}

// ---------------- launch -----------------------------------------------------
extern "C" void kernel_launch(void* const* d_in, const int* in_sizes, int n_in,
                              void* d_out, int out_size){
  const float* x   = (const float*)d_in[0];
  const int*   ei  = (const int*)  d_in[1];
  const float* W1  = (const float*)d_in[2];
  const float* as1 = (const float*)d_in[3];
  const float* ad1 = (const float*)d_in[4];
  const float* b1  = (const float*)d_in[5];
  const float* g1  = (const float*)d_in[6];
  const float* be1 = (const float*)d_in[7];
  const float* W2  = (const float*)d_in[8];
  const float* as2 = (const float*)d_in[9];
  const float* ad2 = (const float*)d_in[10];
  const float* b2  = (const float*)d_in[11];
  const float* g2  = (const float*)d_in[12];
  const float* be2 = (const float*)d_in[13];
  const float* W3  = (const float*)d_in[14];
  const float* as3 = (const float*)d_in[15];
  const float* ad3 = (const float*)d_in[16];
  const float* b3  = (const float*)d_in[17];
  const float* g3  = (const float*)d_in[18];
  const float* be3 = (const float*)d_in[19];
  const float* mW1 = (const float*)d_in[20];
  const float* mb1 = (const float*)d_in[21];
  const float* mW2 = (const float*)d_in[22];
  const float* mb2 = (const float*)d_in[23];
  const float* pW  = (const float*)d_in[24];
  const float* pb  = (const float*)d_in[25];
  const float* vW  = (const float*)d_in[26];
  const float* vb  = (const float*)d_in[27];
  float* out = (float*)d_out;

  const int TB = 256;
  const int gE    = (EE + TB - 1)/TB;
  const int gWarp = (NN*32 + TB - 1)/TB;   // warp-per-node kernels
  const int gAtt  = 592;                   // 4 * 148 SMs
  const int gMlp  = 1184;

  // CSR build (g_deg zeroed at module load / by previous k_scatter)
  k_count<<<gE, TB>>>(ei);
  k_scan1<<<NB1, TB>>>();
  k_scan23c<<<NB1, TB>>>();
  k_scatter<<<gE, TB>>>(ei);

  // layer 1 (D=16, raw x)
  k_att1<<<gAtt, TB>>>(x, W1, as1, ad1);
  k_aggregate<16,true><<<gWarp, TB>>>(x);
  k_out<16><<<GOUT, TB>>>(W1, b1, g1, be1);

  // layer 2 (D=64)
  k_att<<<gAtt, TB>>>(W2, as2, ad2);
  k_aggregate<64,false><<<gWarp, TB>>>(nullptr);
  k_out<64><<<GOUT, TB>>>(W2, b2, g2, be2);

  // layer 3 (D=64)
  k_att<<<gAtt, TB>>>(W3, as3, ad3);
  k_aggregate<64,false><<<gWarp, TB>>>(nullptr);
  k_out<64><<<GOUT, TB>>>(W3, b3, g3, be3);

  // MLP + heads
  k_mlp1<<<gMlp, TB>>>(x, mW1, mb1);
  k_heads<<<gMlp, TB>>>(mW2, mb2, pW, pb, vW, vb, out);
}

// round 6
// speedup vs baseline: 1.1967x; 1.1138x over previous
#include <cuda_runtime.h>
#include <math.h>

#define NN 100000
#define EE 1000000
#define NB1 98     // ceil(NN/1024)
#define GOUT 592   // grid for k_out

typedef unsigned long long ull;

// ---------------- scratch (static device globals; no allocation) -------------
__device__ float g_z[(size_t)NN*128];      // aggregated per-head features
__device__ float g_buf64[(size_t)NN*64];   // layer output (pre-BN)
__device__ float g_as[NN*2];
__device__ float g_ad[NN*2];
__device__ int   g_deg[NN];                // zero-init at load; re-zeroed by k_scatter
__device__ int   g_off[NN];
__device__ int   g_cursor[NN];
__device__ int   g_esrc[EE];
__device__ int   g_bsum[128];
__device__ float g_part[GOUT*128];         // BN partials per k_out block
__device__ float g_bnscale[64];
__device__ float g_bnshift[64];
__device__ int   g_bncnt;

__device__ __forceinline__ float lrelu(float v){ return v > 0.f ? v : 0.2f*v; }

__device__ __forceinline__ ull pk2(float lo, float hi){
  ull u; asm("mov.b64 %0, {%1, %2};" : "=l"(u) : "f"(lo), "f"(hi)); return u;
}
__device__ __forceinline__ void upk2(float& lo, float& hi, ull u){
  asm("mov.b64 {%0, %1}, %2;" : "=f"(lo), "=f"(hi) : "l"(u));
}
#define FMA2(d, a, b, c) \
  asm("fma.rn.f32x2 %0, %1, %2, %3;" : "=l"(d) : "l"(a), "l"(b), "l"(c))

// ---------------- CSR build --------------------------------------------------
__global__ void k_count(const int* __restrict__ ei){
  int e = blockIdx.x*blockDim.x + threadIdx.x;
  if (e < EE) atomicAdd(&g_deg[ei[EE + e]], 1);
}

__global__ void k_scan1(){
  __shared__ int s[256];
  int tid = threadIdx.x;
  int base = blockIdx.x*1024 + tid*4;
  int v[4]; int loc = 0;
  #pragma unroll
  for (int i = 0; i < 4; i++){ int idx = base + i; v[i] = (idx < NN) ? g_deg[idx] : 0; loc += v[i]; }
  s[tid] = loc; __syncthreads();
  #pragma unroll
  for (int d = 1; d < 256; d <<= 1){
    int t = (tid >= d) ? s[tid-d] : 0; __syncthreads();
    s[tid] += t; __syncthreads();
  }
  int run = (tid == 0) ? 0 : s[tid-1];
  #pragma unroll
  for (int i = 0; i < 4; i++){ run += v[i]; int idx = base + i; if (idx < NN) g_off[idx] = run; }
  if (tid == 255) g_bsum[blockIdx.x] = s[255];
}

__global__ void k_scan23c(){
  int tid = threadIdx.x;
  int b = blockIdx.x;
  __shared__ int swarp[8];
  int v = (tid < b) ? g_bsum[tid] : 0;     // b <= 97 < 128
  #pragma unroll
  for (int o = 16; o; o >>= 1) v += __shfl_xor_sync(0xffffffffu, v, o);
  if ((tid & 31) == 0) swarp[tid >> 5] = v;
  __syncthreads();
  int pre = swarp[0] + swarp[1] + swarp[2] + swarp[3];
  int base = b*1024 + tid*4;
  #pragma unroll
  for (int i = 0; i < 4; i++){
    int idx = base + i;
    if (idx < NN){
      int off = g_off[idx] + pre;
      g_off[idx] = off;
      g_cursor[idx] = off - g_deg[idx];
    }
  }
}

__global__ void k_scatter(const int* __restrict__ ei){
  int e = blockIdx.x*blockDim.x + threadIdx.x;
  if (e < EE){
    int s = ei[e], d = ei[EE + e];
    int pos = atomicAdd(&g_cursor[d], 1);
    g_esrc[pos] = s;
  }
  if (e < NN) g_deg[e] = 0;   // re-zero for next replay (deg is dead by now)
}

// ---------------- attention scores (layer 1): raw 16-dim x -------------------
__global__ void __launch_bounds__(256) k_att1(const float* __restrict__ x,
                                              const float* __restrict__ W,
                                              const float* __restrict__ as_,
                                              const float* __restrict__ ad_){
  __shared__ float swa[2][16], swd[2][16];
  int tid = threadIdx.x;
  if (tid < 64){
    int h = (tid >> 4) & 1;
    int k = tid & 15;
    const float* att = (tid < 32) ? as_ : ad_;
    const float* wrow = W + k*128 + h*64;
    float acc = 0.f;
    #pragma unroll 16
    for (int c = 0; c < 64; c++) acc += wrow[c]*att[h*64 + c];
    if (tid < 32) swa[h][k] = acc; else swd[h][k] = acc;
  }
  __syncthreads();
  int lane = tid & 31, w = tid >> 5;
  int k0 = 2*lane;
  bool act = (k0 < 16);
  float wa0a=0,wa0b=0,wa1a=0,wa1b=0,wd0a=0,wd0b=0,wd1a=0,wd1b=0;
  if (act){
    wa0a = swa[0][k0]; wa0b = swa[0][k0+1];
    wa1a = swa[1][k0]; wa1b = swa[1][k0+1];
    wd0a = swd[0][k0]; wd0b = swd[0][k0+1];
    wd1a = swd[1][k0]; wd1b = swd[1][k0+1];
  }
  for (int n = blockIdx.x*8 + w; n < NN; n += gridDim.x*8){
    float2 v = make_float2(0.f, 0.f);
    if (act) v = ((const float2*)(x + (size_t)n*16))[lane];
    float s0 = v.x*wa0a + v.y*wa0b;
    float s1 = v.x*wa1a + v.y*wa1b;
    float d0 = v.x*wd0a + v.y*wd0b;
    float d1 = v.x*wd1a + v.y*wd1b;
    #pragma unroll
    for (int o = 16; o; o >>= 1){
      s0 += __shfl_xor_sync(0xffffffffu, s0, o);
      s1 += __shfl_xor_sync(0xffffffffu, s1, o);
      d0 += __shfl_xor_sync(0xffffffffu, d0, o);
      d1 += __shfl_xor_sync(0xffffffffu, d1, o);
    }
    if (lane == 0){
      g_as[2*n] = s0; g_as[2*n+1] = s1;
      g_ad[2*n] = d0; g_ad[2*n+1] = d1;
    }
  }
}

// ---------------- attention scores (layers 2,3): BN+relu in regs -------------
__global__ void __launch_bounds__(256) k_att2(const float* __restrict__ W,
                                              const float* __restrict__ as_,
                                              const float* __restrict__ ad_){
  __shared__ float swa[2][64], swd[2][64];
  int tid = threadIdx.x;
  {
    int h = (tid >> 6) & 1;
    int k = tid & 63;
    const float* att = (tid < 128) ? as_ : ad_;
    const float* wrow = W + k*128 + h*64;
    float acc = 0.f;
    #pragma unroll 16
    for (int c = 0; c < 64; c++) acc += wrow[c]*att[h*64 + c];
    if (tid < 128) swa[h][k] = acc; else swd[h][k] = acc;
  }
  int lane = tid & 31, w = tid >> 5;
  float2 sc2 = ((const float2*)g_bnscale)[lane];
  float2 sh2 = ((const float2*)g_bnshift)[lane];
  __syncthreads();
  int k0 = 2*lane;
  float wa0a = swa[0][k0], wa0b = swa[0][k0+1];
  float wa1a = swa[1][k0], wa1b = swa[1][k0+1];
  float wd0a = swd[0][k0], wd0b = swd[0][k0+1];
  float wd1a = swd[1][k0], wd1b = swd[1][k0+1];
  for (int n = blockIdx.x*8 + w; n < NN; n += gridDim.x*8){
    float2 v = ((const float2*)(g_buf64 + (size_t)n*64))[lane];
    v.x = fmaxf(fmaf(v.x, sc2.x, sh2.x), 0.f);
    v.y = fmaxf(fmaf(v.y, sc2.y, sh2.y), 0.f);
    float s0 = v.x*wa0a + v.y*wa0b;
    float s1 = v.x*wa1a + v.y*wa1b;
    float d0 = v.x*wd0a + v.y*wd0b;
    float d1 = v.x*wd1a + v.y*wd1b;
    #pragma unroll
    for (int o = 16; o; o >>= 1){
      s0 += __shfl_xor_sync(0xffffffffu, s0, o);
      s1 += __shfl_xor_sync(0xffffffffu, s1, o);
      d0 += __shfl_xor_sync(0xffffffffu, d0, o);
      d1 += __shfl_xor_sync(0xffffffffu, d1, o);
    }
    if (lane == 0){
      g_as[2*n] = s0; g_as[2*n+1] = s1;
      g_ad[2*n] = d0; g_ad[2*n+1] = d1;
    }
  }
}

// ---------------- GAT aggregation (BN folded into gather for layers 2,3) -----
template<int D, bool BN>
__global__ void __launch_bounds__(256) k_aggregate(const float* __restrict__ xin){
  const float* xsrc = BN ? (const float*)g_buf64 : xin;
  int t = blockIdx.x*blockDim.x + threadIdx.x;
  int n = t >> 5, lane = t & 31;
  if (n >= NN) return;
  int k0 = 2*lane;
  bool act = (k0 < D);
  float2 sc2 = make_float2(0.f,0.f), sh2 = make_float2(0.f,0.f);
  if (BN && act){ sc2 = ((const float2*)g_bnscale)[lane]; sh2 = ((const float2*)g_bnshift)[lane]; }
  int start = n ? g_off[n-1] : 0;
  int end   = g_off[n];
  int len   = end - start;
  float ad0 = g_ad[2*n], ad1 = g_ad[2*n+1];
  float es0 = lrelu(g_as[2*n]   + ad0);   // self loop
  float es1 = lrelu(g_as[2*n+1] + ad1);
  float2 vself = make_float2(0.f, 0.f);
  if (act){
    vself = ((const float2*)(xsrc + (size_t)n*D))[lane];
    if (BN){
      vself.x = fmaxf(fmaf(vself.x, sc2.x, sh2.x), 0.f);
      vself.y = fmaxf(fmaf(vself.y, sc2.y, sh2.y), 0.f);
    }
  }

  float2 y0, y1;
  float den0, den1;

  if (len <= 32){
    int s = 0; float e0 = -1e30f, e1 = -1e30f;
    if (lane < len){
      s = g_esrc[start + lane];
      float2 asv = ((const float2*)g_as)[s];
      e0 = lrelu(asv.x + ad0);
      e1 = lrelu(asv.y + ad1);
    }
    float m0 = fmaxf(e0, es0), m1 = fmaxf(e1, es1);
    #pragma unroll
    for (int o = 16; o; o >>= 1){
      m0 = fmaxf(m0, __shfl_xor_sync(0xffffffffu, m0, o));
      m1 = fmaxf(m1, __shfl_xor_sync(0xffffffffu, m1, o));
    }
    float w0 = (lane < len) ? __expf(e0 - m0) : 0.f;
    float w1 = (lane < len) ? __expf(e1 - m1) : 0.f;
    float d0 = w0, d1 = w1;
    #pragma unroll
    for (int o = 16; o; o >>= 1){
      d0 += __shfl_xor_sync(0xffffffffu, d0, o);
      d1 += __shfl_xor_sync(0xffffffffu, d1, o);
    }
    float ws0 = __expf(es0 - m0), ws1 = __expf(es1 - m1);
    den0 = d0 + ws0 + 1e-16f;
    den1 = d1 + ws1 + 1e-16f;
    y0.x = ws0*vself.x; y0.y = ws0*vself.y;
    y1.x = ws1*vself.x; y1.y = ws1*vself.y;
    #pragma unroll 4
    for (int k = 0; k < len; k++){
      int   sk  = __shfl_sync(0xffffffffu, s,  k);
      float wk0 = __shfl_sync(0xffffffffu, w0, k);
      float wk1 = __shfl_sync(0xffffffffu, w1, k);
      float2 v = make_float2(0.f, 0.f);
      if (act){
        v = ((const float2*)(xsrc + (size_t)sk*D))[lane];
        if (BN){
          v.x = fmaxf(fmaf(v.x, sc2.x, sh2.x), 0.f);
          v.y = fmaxf(fmaf(v.y, sc2.y, sh2.y), 0.f);
        }
      }
      y0.x += wk0*v.x; y0.y += wk0*v.y;
      y1.x += wk1*v.x; y1.y += wk1*v.y;
    }
  } else {
    float m0 = es0, m1 = es1;
    for (int i = start + lane; i < end; i += 32){
      int s = g_esrc[i];
      float2 asv = ((const float2*)g_as)[s];
      m0 = fmaxf(m0, lrelu(asv.x + ad0));
      m1 = fmaxf(m1, lrelu(asv.y + ad1));
    }
    #pragma unroll
    for (int o = 16; o; o >>= 1){
      m0 = fmaxf(m0, __shfl_xor_sync(0xffffffffu, m0, o));
      m1 = fmaxf(m1, __shfl_xor_sync(0xffffffffu, m1, o));
    }
    float ws0 = __expf(es0 - m0), ws1 = __expf(es1 - m1);
    y0.x = ws0*vself.x; y0.y = ws0*vself.y;
    y1.x = ws1*vself.x; y1.y = ws1*vself.y;
    float d0 = 0.f, d1 = 0.f;
    for (int base = start; base < end; base += 32){
      int cnt = min(32, end - base);
      int s = 0; float w0 = 0.f, w1 = 0.f;
      if (lane < cnt){
        s = g_esrc[base + lane];
        float2 asv = ((const float2*)g_as)[s];
        w0 = __expf(lrelu(asv.x + ad0) - m0);
        w1 = __expf(lrelu(asv.y + ad1) - m1);
      }
      d0 += w0; d1 += w1;
      for (int k = 0; k < cnt; k++){
        int   sk  = __shfl_sync(0xffffffffu, s,  k);
        float wk0 = __shfl_sync(0xffffffffu, w0, k);
        float wk1 = __shfl_sync(0xffffffffu, w1, k);
        float2 v = make_float2(0.f, 0.f);
        if (act){
          v = ((const float2*)(xsrc + (size_t)sk*D))[lane];
          if (BN){
            v.x = fmaxf(fmaf(v.x, sc2.x, sh2.x), 0.f);
            v.y = fmaxf(fmaf(v.y, sc2.y, sh2.y), 0.f);
          }
        }
        y0.x += wk0*v.x; y0.y += wk0*v.y;
        y1.x += wk1*v.x; y1.y += wk1*v.y;
      }
    }
    #pragma unroll
    for (int o = 16; o; o >>= 1){
      d0 += __shfl_xor_sync(0xffffffffu, d0, o);
      d1 += __shfl_xor_sync(0xffffffffu, d1, o);
    }
    den0 = d0 + ws0 + 1e-16f;
    den1 = d1 + ws1 + 1e-16f;
  }

  if (act){
    float i0 = 1.f/den0, i1 = 1.f/den1;
    float* zr = g_z + (size_t)n*(2*D);
    ((float2*)(zr))[lane]     = make_float2(y0.x*i0, y0.y*i0);
    ((float2*)(zr + D))[lane] = make_float2(y1.x*i1, y1.y*i1);
  }
}

// ---------------- output transform: 8 nodes per barrier pair -----------------
// thread (g, j, hb): j = (tid&127)>>1, hb = tid&1; head-combine via shfl_xor(1).
template<int D>
__global__ void __launch_bounds__(256) k_out(const float* __restrict__ W,
                                             const float* __restrict__ b,
                                             const float* __restrict__ gam,
                                             const float* __restrict__ bet){
  int tid = threadIdx.x;
  int g   = tid >> 7;
  int idx = tid & 127;
  int j   = idx >> 1;
  int hb  = idx & 1;
  ull wp[D/2];
  #pragma unroll
  for (int k2 = 0; k2 < D/2; k2++)
    wp[k2] = pk2(0.5f*W[(2*k2)*128 + hb*64 + j], 0.5f*W[(2*k2+1)*128 + hb*64 + j]);
  float bj = b[j];
  __shared__ __align__(16) float sy[8][2*D];
  __shared__ float sacc[256];
  float bs = 0.f, bq = 0.f;
  const int F4 = D/2;                  // float4 per row
  for (int n0 = blockIdx.x*8; n0 < NN; n0 += GOUT*8){
    if (tid < 4*D){
      int row = tid / F4;
      int col = tid % F4;
      int n = n0 + row;
      if (n < NN)
        ((float4*)sy[row])[col] = ((const float4*)(g_z + (size_t)n*(2*D)))[col];
    }
    __syncthreads();
    #pragma unroll
    for (int i = 0; i < 4; i++){
      int n = n0 + g*4 + i;
      const ull* yp = (const ull*)(sy[g*4+i] + hb*D);
      ull a0 = 0ull, a1 = 0ull;
      #pragma unroll
      for (int k2 = 0; k2 < D/2; k2 += 2){
        FMA2(a0, yp[k2],   wp[k2],   a0);
        FMA2(a1, yp[k2+1], wp[k2+1], a1);
      }
      float l0,h0,l1,h1; upk2(l0,h0,a0); upk2(l1,h1,a1);
      float partial = (l0+h0)+(l1+h1);
      float comb = partial + __shfl_xor_sync(0xffffffffu, partial, 1);
      if (hb == 0 && n < NN){
        float r = comb + bj;
        g_buf64[(size_t)n*64 + j] = r;
        bs += r; bq += r*r;
      }
    }
    __syncthreads();
  }
  // BN partials: hb==0 thread for (g, j) sits at tid = g*128 + 2*j
  sacc[tid] = bs;
  __syncthreads();
  float ts = 0.f;
  if (tid < 64) ts = sacc[2*tid] + sacc[128 + 2*tid];
  __syncthreads();
  sacc[tid] = bq;
  __syncthreads();
  if (tid < 64){
    g_part[blockIdx.x*128 + tid]      = ts;
    g_part[blockIdx.x*128 + 64 + tid] = sacc[2*tid] + sacc[128 + 2*tid];
  }
  __threadfence();
  __shared__ bool lastb;
  if (tid == 0){
    lastb = (atomicAdd(&g_bncnt, 1) == GOUT-1);
    if (lastb) g_bncnt = 0;
  }
  __syncthreads();
  if (lastb && tid < 64){
    float ss = 0.f, qq = 0.f;
    #pragma unroll 8
    for (int bb = 0; bb < GOUT; bb++){
      ss += __ldcg(&g_part[bb*128 + tid]);
      qq += __ldcg(&g_part[bb*128 + 64 + tid]);
    }
    const float inv = 1.f/(float)NN;
    float mean = ss*inv;
    float var  = qq*inv - mean*mean;
    float rstd = rsqrtf(var + 1e-5f);
    float scv = rstd*gam[tid];
    g_bnscale[tid] = scv;
    g_bnshift[tid] = bet[tid] - mean*scv;
  }
}

// ---------------- MLP1 + heads fused (BN3 at load, hidden never stored) ------
__global__ void __launch_bounds__(256) k_mlp1h(const float* __restrict__ x,
                                               const float* __restrict__ W,
                                               const float* __restrict__ b,
                                               const float* __restrict__ W2,
                                               const float* __restrict__ b2,
                                               const float* __restrict__ pW,
                                               const float* __restrict__ pb,
                                               const float* __restrict__ vW,
                                               const float* __restrict__ vb,
                                               float* __restrict__ out){
  __shared__ float sq[64], sv[64], scst[2];
  __shared__ __align__(16) float sh[4][72];
  __shared__ float spart[8][2];
  int tid = threadIdx.x;
  int j = tid & 63, g = tid >> 6;
  if (tid < 128){
    int k = tid & 63;
    const float* hv = (tid < 64) ? pW : vW;
    const float* row = W2 + k*64;
    float acc = 0.f;
    #pragma unroll 16
    for (int c = 0; c < 64; c++) acc += row[c]*hv[c];
    if (tid < 64) sq[k] = acc; else sv[k] = acc;
  } else if (tid == 128){
    float a = 0.f, c = 0.f;
    #pragma unroll 16
    for (int jj = 0; jj < 64; jj++){ a += b2[jj]*pW[jj]; c += b2[jj]*vW[jj]; }
    scst[0] = a + pb[0];
    scst[1] = c + vb[0];
  }
  ull wp[34];
  #pragma unroll
  for (int k2 = 0; k2 < 34; k2++)
    wp[k2] = pk2(W[(2*k2)*64 + j], W[(2*k2+1)*64 + j]);
  float w68 = W[68*64 + j];
  float bj = b[j];
  float4 sc4, sh4;
  if (j < 16){
    sc4 = ((const float4*)g_bnscale)[j];
    sh4 = ((const float4*)g_bnshift)[j];
  }
  for (int n0 = blockIdx.x*4; n0 < NN; n0 += gridDim.x*4){
    int n = n0 + g;
    if (n < NN){
      if (j < 16){
        float4 v = ((const float4*)(g_buf64 + (size_t)n*64))[j];
        v.x = fmaxf(fmaf(v.x, sc4.x, sh4.x), 0.f);
        v.y = fmaxf(fmaf(v.y, sc4.y, sh4.y), 0.f);
        v.z = fmaxf(fmaf(v.z, sc4.z, sh4.z), 0.f);
        v.w = fmaxf(fmaf(v.w, sc4.w, sh4.w), 0.f);
        ((float4*)sh[g])[j] = v;
      }
      if (j >= 16 && j < 21) sh[g][48 + j] = x[(size_t)n*16 + (j - 7)];  // ctx = x[:,9:14]
    }
    __syncthreads();
    float lp = 0.f, vp = 0.f;
    {
      ull a0 = 0ull, a1 = 0ull;
      const ull* yp = (const ull*)sh[g];
      #pragma unroll
      for (int k2 = 0; k2 < 34; k2 += 2){
        FMA2(a0, yp[k2],   wp[k2],   a0);
        FMA2(a1, yp[k2+1], wp[k2+1], a1);
      }
      float l0,h0,l1,h1; upk2(l0,h0,a0); upk2(l1,h1,a1);
      float t = fmaxf((l0+h0)+(l1+h1) + sh[g][68]*w68 + bj, 0.f);
      if (n < NN){ lp = t*sq[j]; vp = t*sv[j]; }
    }
    #pragma unroll
    for (int o = 16; o; o >>= 1){
      lp += __shfl_xor_sync(0xffffffffu, lp, o);
      vp += __shfl_xor_sync(0xffffffffu, vp, o);
    }
    int w = tid >> 5;
    if ((tid & 31) == 0){ spart[w][0] = lp; spart[w][1] = vp; }
    __syncthreads();
    if (tid < 4){
      int nn = n0 + tid;
      if (nn < NN){
        out[nn]      = spart[2*tid][0] + spart[2*tid+1][0] + scst[0];
        out[NN + nn] = spart[2*tid][1] + spart[2*tid+1][1] + scst[1];
      }
    }
    __syncthreads();
  }
}

// ---------------- launch -----------------------------------------------------
extern "C" void kernel_launch(void* const* d_in, const int* in_sizes, int n_in,
                              void* d_out, int out_size){
  const float* x   = (const float*)d_in[0];
  const int*   ei  = (const int*)  d_in[1];
  const float* W1  = (const float*)d_in[2];
  const float* as1 = (const float*)d_in[3];
  const float* ad1 = (const float*)d_in[4];
  const float* b1  = (const float*)d_in[5];
  const float* g1  = (const float*)d_in[6];
  const float* be1 = (const float*)d_in[7];
  const float* W2  = (const float*)d_in[8];
  const float* as2 = (const float*)d_in[9];
  const float* ad2 = (const float*)d_in[10];
  const float* b2  = (const float*)d_in[11];
  const float* g2  = (const float*)d_in[12];
  const float* be2 = (const float*)d_in[13];
  const float* W3  = (const float*)d_in[14];
  const float* as3 = (const float*)d_in[15];
  const float* ad3 = (const float*)d_in[16];
  const float* b3  = (const float*)d_in[17];
  const float* g3  = (const float*)d_in[18];
  const float* be3 = (const float*)d_in[19];
  const float* mW1 = (const float*)d_in[20];
  const float* mb1 = (const float*)d_in[21];
  const float* mW2 = (const float*)d_in[22];
  const float* mb2 = (const float*)d_in[23];
  const float* pW  = (const float*)d_in[24];
  const float* pb  = (const float*)d_in[25];
  const float* vW  = (const float*)d_in[26];
  const float* vb  = (const float*)d_in[27];
  float* out = (float*)d_out;

  const int TB = 256;
  const int gE    = (EE + TB - 1)/TB;
  const int gWarp = (NN*32 + TB - 1)/TB;
  const int gAtt  = 592;
  const int gMlp  = 1184;

  // CSR + att1 (k_att1 placed 4th so ncu's capture window profiles it;
  // k_scatter only depends on k_scan23c, so this order is valid)
  k_count<<<gE, TB>>>(ei);
  k_scan1<<<NB1, TB>>>();
  k_scan23c<<<NB1, TB>>>();
  k_att1<<<gAtt, TB>>>(x, W1, as1, ad1);
  k_scatter<<<gE, TB>>>(ei);

  // layer 1 (D=16, raw x, no BN)
  k_aggregate<16,false><<<gWarp, TB>>>(x);
  k_out<16><<<GOUT, TB>>>(W1, b1, g1, be1);

  // layer 2 (D=64, BN folded into gather)
  k_att2<<<gAtt, TB>>>(W2, as2, ad2);
  k_aggregate<64,true><<<gWarp, TB>>>(nullptr);
  k_out<64><<<GOUT, TB>>>(W2, b2, g2, be2);

  // layer 3
  k_att2<<<gAtt, TB>>>(W3, as3, ad3);
  k_aggregate<64,true><<<gWarp, TB>>>(nullptr);
  k_out<64><<<GOUT, TB>>>(W3, b3, g3, be3);

  // MLP + heads (fused)
  k_mlp1h<<<gMlp, TB>>>(x, mW1, mb1, mW2, mb2, pW, pb, vW, vb, out);
}

// round 7
// speedup vs baseline: 1.2647x; 1.0568x over previous
#include <cuda_runtime.h>
#include <math.h>

#define NN 100000
#define EE 1000000
#define NB1 98     // ceil(NN/1024)
#define GOUT 592   // grid for k_out

typedef unsigned long long ull;

// ---------------- scratch (static device globals; no allocation) -------------
__device__ float  g_z[(size_t)NN*128];     // aggregated per-head features
__device__ float  g_buf64[(size_t)NN*64];  // layer output (pre-BN)
__device__ float  g_as[NN*2];              // per-edge src scores
__device__ float4 g_att[NN];               // (as0, as1, ad0, ad1) per node
__device__ int    g_deg[NN];               // zero-init; re-zeroed by k_scatter
__device__ int    g_off[NN];
__device__ int    g_cursor[NN];
__device__ int    g_esrc[EE];
__device__ int    g_bsum[128];
__device__ float  g_part[GOUT*128];        // BN partials per k_out block
__device__ float  g_bnscale[64];
__device__ float  g_bnshift[64];
__device__ int    g_bncnt;

__device__ __forceinline__ float lrelu(float v){ return v > 0.f ? v : 0.2f*v; }

__device__ __forceinline__ ull pk2(float lo, float hi){
  ull u; asm("mov.b64 %0, {%1, %2};" : "=l"(u) : "f"(lo), "f"(hi)); return u;
}
__device__ __forceinline__ void upk2(float& lo, float& hi, ull u){
  asm("mov.b64 {%0, %1}, %2;" : "=f"(lo), "=f"(hi) : "l"(u));
}
#define FMA2(d, a, b, c) \
  asm("fma.rn.f32x2 %0, %1, %2, %3;" : "=l"(d) : "l"(a), "l"(b), "l"(c))

// ---------------- CSR build --------------------------------------------------
__global__ void k_count(const int* __restrict__ ei){
  int e = blockIdx.x*blockDim.x + threadIdx.x;
  if (e < EE) atomicAdd(&g_deg[ei[EE + e]], 1);
}

__global__ void k_scan1(){
  __shared__ int s[256];
  int tid = threadIdx.x;
  int base = blockIdx.x*1024 + tid*4;
  int v[4]; int loc = 0;
  #pragma unroll
  for (int i = 0; i < 4; i++){ int idx = base + i; v[i] = (idx < NN) ? g_deg[idx] : 0; loc += v[i]; }
  s[tid] = loc; __syncthreads();
  #pragma unroll
  for (int d = 1; d < 256; d <<= 1){
    int t = (tid >= d) ? s[tid-d] : 0; __syncthreads();
    s[tid] += t; __syncthreads();
  }
  int run = (tid == 0) ? 0 : s[tid-1];
  #pragma unroll
  for (int i = 0; i < 4; i++){ run += v[i]; int idx = base + i; if (idx < NN) g_off[idx] = run; }
  if (tid == 255) g_bsum[blockIdx.x] = s[255];
}

__global__ void k_scan23c(){
  int tid = threadIdx.x;
  int b = blockIdx.x;
  __shared__ int swarp[8];
  int v = (tid < b) ? g_bsum[tid] : 0;     // b <= 97 < 128
  #pragma unroll
  for (int o = 16; o; o >>= 1) v += __shfl_xor_sync(0xffffffffu, v, o);
  if ((tid & 31) == 0) swarp[tid >> 5] = v;
  __syncthreads();
  int pre = swarp[0] + swarp[1] + swarp[2] + swarp[3];
  int base = b*1024 + tid*4;
  #pragma unroll
  for (int i = 0; i < 4; i++){
    int idx = base + i;
    if (idx < NN){
      int off = g_off[idx] + pre;
      g_off[idx] = off;
      g_cursor[idx] = off - g_deg[idx];
    }
  }
}

__global__ void k_scatter(const int* __restrict__ ei){
  int e = blockIdx.x*blockDim.x + threadIdx.x;
  if (e < EE){
    int s = ei[e], d = ei[EE + e];
    int pos = atomicAdd(&g_cursor[d], 1);
    g_esrc[pos] = s;
  }
  if (e < NN) g_deg[e] = 0;   // re-zero for next replay (deg is dead by now)
}

// ---------------- attention scores (layer 1): thread-per-node ----------------
__global__ void __launch_bounds__(256) k_att1(const float* __restrict__ x,
                                              const float* __restrict__ W,
                                              const float* __restrict__ as_,
                                              const float* __restrict__ ad_){
  __shared__ float swa[2][16], swd[2][16];
  int tid = threadIdx.x;
  if (tid < 64){
    int h = (tid >> 4) & 1;
    int k = tid & 15;
    const float* att = (tid < 32) ? as_ : ad_;
    const float* wrow = W + k*128 + h*64;
    float acc = 0.f;
    #pragma unroll 16
    for (int c = 0; c < 64; c++) acc += wrow[c]*att[h*64 + c];
    if (tid < 32) swa[h][k] = acc; else swd[h][k] = acc;
  }
  __syncthreads();
  int n = blockIdx.x*blockDim.x + tid;
  if (n >= NN) return;
  float s0 = 0.f, s1 = 0.f, d0 = 0.f, d1 = 0.f;
  const float4* xr = (const float4*)(x + (size_t)n*16);
  #pragma unroll
  for (int q = 0; q < 4; q++){
    float4 v = xr[q];
    int k = 4*q;
    s0 += v.x*swa[0][k] + v.y*swa[0][k+1] + v.z*swa[0][k+2] + v.w*swa[0][k+3];
    s1 += v.x*swa[1][k] + v.y*swa[1][k+1] + v.z*swa[1][k+2] + v.w*swa[1][k+3];
    d0 += v.x*swd[0][k] + v.y*swd[0][k+1] + v.z*swd[0][k+2] + v.w*swd[0][k+3];
    d1 += v.x*swd[1][k] + v.y*swd[1][k+1] + v.z*swd[1][k+2] + v.w*swd[1][k+3];
  }
  ((float2*)g_as)[n] = make_float2(s0, s1);
  g_att[n] = make_float4(s0, s1, d0, d1);
}

// ---------------- attention scores (layers 2,3): thread-per-node, BN in regs -
__global__ void __launch_bounds__(256) k_att2(const float* __restrict__ W,
                                              const float* __restrict__ as_,
                                              const float* __restrict__ ad_){
  __shared__ float swa[2][64], swd[2][64];
  __shared__ float sbs[64], sbh[64];
  int tid = threadIdx.x;
  {
    int h = (tid >> 6) & 1;
    int k = tid & 63;
    const float* att = (tid < 128) ? as_ : ad_;
    const float* wrow = W + k*128 + h*64;
    float acc = 0.f;
    #pragma unroll 16
    for (int c = 0; c < 64; c++) acc += wrow[c]*att[h*64 + c];
    if (tid < 128) swa[h][k] = acc; else swd[h][k] = acc;
    if (tid < 64){ sbs[tid] = g_bnscale[tid]; sbh[tid] = g_bnshift[tid]; }
  }
  __syncthreads();
  int n = blockIdx.x*blockDim.x + tid;
  if (n >= NN) return;
  float s0 = 0.f, s1 = 0.f, d0 = 0.f, d1 = 0.f;
  const float4* xr = (const float4*)(g_buf64 + (size_t)n*64);
  #pragma unroll
  for (int q = 0; q < 16; q++){
    float4 v = xr[q];
    int k = 4*q;
    v.x = fmaxf(fmaf(v.x, sbs[k],   sbh[k]),   0.f);
    v.y = fmaxf(fmaf(v.y, sbs[k+1], sbh[k+1]), 0.f);
    v.z = fmaxf(fmaf(v.z, sbs[k+2], sbh[k+2]), 0.f);
    v.w = fmaxf(fmaf(v.w, sbs[k+3], sbh[k+3]), 0.f);
    s0 += v.x*swa[0][k] + v.y*swa[0][k+1] + v.z*swa[0][k+2] + v.w*swa[0][k+3];
    s1 += v.x*swa[1][k] + v.y*swa[1][k+1] + v.z*swa[1][k+2] + v.w*swa[1][k+3];
    d0 += v.x*swd[0][k] + v.y*swd[0][k+1] + v.z*swd[0][k+2] + v.w*swd[0][k+3];
    d1 += v.x*swd[1][k] + v.y*swd[1][k+1] + v.z*swd[1][k+2] + v.w*swd[1][k+3];
  }
  ((float2*)g_as)[n] = make_float2(s0, s1);
  g_att[n] = make_float4(s0, s1, d0, d1);
}

// ---------------- GAT aggregation (BN folded into gather for layers 2,3) -----
template<int D, bool BN>
__global__ void __launch_bounds__(256) k_aggregate(const float* __restrict__ xin){
  const float* xsrc = BN ? (const float*)g_buf64 : xin;
  int t = blockIdx.x*blockDim.x + threadIdx.x;
  int n = t >> 5, lane = t & 31;
  if (n >= NN) return;
  int k0 = 2*lane;
  bool act = (k0 < D);
  float2 sc2 = make_float2(0.f,0.f), sh2 = make_float2(0.f,0.f);
  if (BN && act){ sc2 = ((const float2*)g_bnscale)[lane]; sh2 = ((const float2*)g_bnshift)[lane]; }
  int start = n ? g_off[n-1] : 0;
  int end   = g_off[n];
  int len   = end - start;
  float4 attn = g_att[n];
  float ad0 = attn.z, ad1 = attn.w;
  float es0 = lrelu(attn.x + ad0);   // self loop
  float es1 = lrelu(attn.y + ad1);
  float2 vself = make_float2(0.f, 0.f);
  if (act){
    vself = ((const float2*)(xsrc + (size_t)n*D))[lane];
    if (BN){
      vself.x = fmaxf(fmaf(vself.x, sc2.x, sh2.x), 0.f);
      vself.y = fmaxf(fmaf(vself.y, sc2.y, sh2.y), 0.f);
    }
  }

  float2 y0, y1;
  float den0, den1;

  if (len <= 32){
    int s = 0; float e0 = -1e30f, e1 = -1e30f;
    if (lane < len){
      s = g_esrc[start + lane];
      float2 asv = ((const float2*)g_as)[s];
      e0 = lrelu(asv.x + ad0);
      e1 = lrelu(asv.y + ad1);
    }
    float m0 = fmaxf(e0, es0), m1 = fmaxf(e1, es1);
    #pragma unroll
    for (int o = 16; o; o >>= 1){
      m0 = fmaxf(m0, __shfl_xor_sync(0xffffffffu, m0, o));
      m1 = fmaxf(m1, __shfl_xor_sync(0xffffffffu, m1, o));
    }
    float w0 = (lane < len) ? __expf(e0 - m0) : 0.f;
    float w1 = (lane < len) ? __expf(e1 - m1) : 0.f;
    float d0 = w0, d1 = w1;
    #pragma unroll
    for (int o = 16; o; o >>= 1){
      d0 += __shfl_xor_sync(0xffffffffu, d0, o);
      d1 += __shfl_xor_sync(0xffffffffu, d1, o);
    }
    float ws0 = __expf(es0 - m0), ws1 = __expf(es1 - m1);
    den0 = d0 + ws0 + 1e-16f;
    den1 = d1 + ws1 + 1e-16f;
    y0.x = ws0*vself.x; y0.y = ws0*vself.y;
    y1.x = ws1*vself.x; y1.y = ws1*vself.y;
    #pragma unroll 4
    for (int k = 0; k < len; k++){
      int   sk  = __shfl_sync(0xffffffffu, s,  k);
      float wk0 = __shfl_sync(0xffffffffu, w0, k);
      float wk1 = __shfl_sync(0xffffffffu, w1, k);
      float2 v = make_float2(0.f, 0.f);
      if (act){
        v = ((const float2*)(xsrc + (size_t)sk*D))[lane];
        if (BN){
          v.x = fmaxf(fmaf(v.x, sc2.x, sh2.x), 0.f);
          v.y = fmaxf(fmaf(v.y, sc2.y, sh2.y), 0.f);
        }
      }
      y0.x += wk0*v.x; y0.y += wk0*v.y;
      y1.x += wk1*v.x; y1.y += wk1*v.y;
    }
  } else {
    float m0 = es0, m1 = es1;
    for (int i = start + lane; i < end; i += 32){
      int s = g_esrc[i];
      float2 asv = ((const float2*)g_as)[s];
      m0 = fmaxf(m0, lrelu(asv.x + ad0));
      m1 = fmaxf(m1, lrelu(asv.y + ad1));
    }
    #pragma unroll
    for (int o = 16; o; o >>= 1){
      m0 = fmaxf(m0, __shfl_xor_sync(0xffffffffu, m0, o));
      m1 = fmaxf(m1, __shfl_xor_sync(0xffffffffu, m1, o));
    }
    float ws0 = __expf(es0 - m0), ws1 = __expf(es1 - m1);
    y0.x = ws0*vself.x; y0.y = ws0*vself.y;
    y1.x = ws1*vself.x; y1.y = ws1*vself.y;
    float d0 = 0.f, d1 = 0.f;
    for (int base = start; base < end; base += 32){
      int cnt = min(32, end - base);
      int s = 0; float w0 = 0.f, w1 = 0.f;
      if (lane < cnt){
        s = g_esrc[base + lane];
        float2 asv = ((const float2*)g_as)[s];
        w0 = __expf(lrelu(asv.x + ad0) - m0);
        w1 = __expf(lrelu(asv.y + ad1) - m1);
      }
      d0 += w0; d1 += w1;
      for (int k = 0; k < cnt; k++){
        int   sk  = __shfl_sync(0xffffffffu, s,  k);
        float wk0 = __shfl_sync(0xffffffffu, w0, k);
        float wk1 = __shfl_sync(0xffffffffu, w1, k);
        float2 v = make_float2(0.f, 0.f);
        if (act){
          v = ((const float2*)(xsrc + (size_t)sk*D))[lane];
          if (BN){
            v.x = fmaxf(fmaf(v.x, sc2.x, sh2.x), 0.f);
            v.y = fmaxf(fmaf(v.y, sc2.y, sh2.y), 0.f);
          }
        }
        y0.x += wk0*v.x; y0.y += wk0*v.y;
        y1.x += wk1*v.x; y1.y += wk1*v.y;
      }
    }
    #pragma unroll
    for (int o = 16; o; o >>= 1){
      d0 += __shfl_xor_sync(0xffffffffu, d0, o);
      d1 += __shfl_xor_sync(0xffffffffu, d1, o);
    }
    den0 = d0 + ws0 + 1e-16f;
    den1 = d1 + ws1 + 1e-16f;
  }

  if (act){
    float i0 = 1.f/den0, i1 = 1.f/den1;
    float* zr = g_z + (size_t)n*(2*D);
    ((float2*)(zr))[lane]     = make_float2(y0.x*i0, y0.y*i0);
    ((float2*)(zr + D))[lane] = make_float2(y1.x*i1, y1.y*i1);
  }
}

// ---------------- output transform: 8 nodes per barrier pair -----------------
template<int D>
__global__ void __launch_bounds__(256) k_out(const float* __restrict__ W,
                                             const float* __restrict__ b,
                                             const float* __restrict__ gam,
                                             const float* __restrict__ bet){
  int tid = threadIdx.x;
  int g   = tid >> 7;
  int idx = tid & 127;
  int j   = idx >> 1;
  int hb  = idx & 1;
  ull wp[D/2];
  #pragma unroll
  for (int k2 = 0; k2 < D/2; k2++)
    wp[k2] = pk2(0.5f*W[(2*k2)*128 + hb*64 + j], 0.5f*W[(2*k2+1)*128 + hb*64 + j]);
  float bj = b[j];
  __shared__ __align__(16) float sy[8][2*D];
  __shared__ float sacc[256];
  float bs = 0.f, bq = 0.f;
  const int F4 = D/2;                  // float4 per row
  for (int n0 = blockIdx.x*8; n0 < NN; n0 += GOUT*8){
    if (tid < 4*D){
      int row = tid / F4;
      int col = tid % F4;
      int n = n0 + row;
      if (n < NN)
        ((float4*)sy[row])[col] = ((const float4*)(g_z + (size_t)n*(2*D)))[col];
    }
    __syncthreads();
    #pragma unroll
    for (int i = 0; i < 4; i++){
      int n = n0 + g*4 + i;
      const ull* yp = (const ull*)(sy[g*4+i] + hb*D);
      ull a0 = 0ull, a1 = 0ull;
      #pragma unroll
      for (int k2 = 0; k2 < D/2; k2 += 2){
        FMA2(a0, yp[k2],   wp[k2],   a0);
        FMA2(a1, yp[k2+1], wp[k2+1], a1);
      }
      float l0,h0,l1,h1; upk2(l0,h0,a0); upk2(l1,h1,a1);
      float partial = (l0+h0)+(l1+h1);
      float comb = partial + __shfl_xor_sync(0xffffffffu, partial, 1);
      if (hb == 0 && n < NN){
        float r = comb + bj;
        g_buf64[(size_t)n*64 + j] = r;
        bs += r; bq += r*r;
      }
    }
    __syncthreads();
  }
  sacc[tid] = bs;
  __syncthreads();
  float ts = 0.f;
  if (tid < 64) ts = sacc[2*tid] + sacc[128 + 2*tid];
  __syncthreads();
  sacc[tid] = bq;
  __syncthreads();
  if (tid < 64){
    g_part[blockIdx.x*128 + tid]      = ts;
    g_part[blockIdx.x*128 + 64 + tid] = sacc[2*tid] + sacc[128 + 2*tid];
  }
  __threadfence();
  __shared__ bool lastb;
  if (tid == 0){
    lastb = (atomicAdd(&g_bncnt, 1) == GOUT-1);
    if (lastb) g_bncnt = 0;
  }
  __syncthreads();
  if (lastb && tid < 64){
    float ss = 0.f, qq = 0.f;
    #pragma unroll 8
    for (int bb = 0; bb < GOUT; bb++){
      ss += __ldcg(&g_part[bb*128 + tid]);
      qq += __ldcg(&g_part[bb*128 + 64 + tid]);
    }
    const float inv = 1.f/(float)NN;
    float mean = ss*inv;
    float var  = qq*inv - mean*mean;
    float rstd = rsqrtf(var + 1e-5f);
    float scv = rstd*gam[tid];
    g_bnscale[tid] = scv;
    g_bnshift[tid] = bet[tid] - mean*scv;
  }
}

// ---------------- MLP1 + heads fused (BN3 at load, hidden never stored) ------
__global__ void __launch_bounds__(256) k_mlp1h(const float* __restrict__ x,
                                               const float* __restrict__ W,
                                               const float* __restrict__ b,
                                               const float* __restrict__ W2,
                                               const float* __restrict__ b2,
                                               const float* __restrict__ pW,
                                               const float* __restrict__ pb,
                                               const float* __restrict__ vW,
                                               const float* __restrict__ vb,
                                               float* __restrict__ out){
  __shared__ float sq[64], sv[64], scst[2];
  __shared__ __align__(16) float sh[4][72];
  __shared__ float spart[8][2];
  int tid = threadIdx.x;
  int j = tid & 63, g = tid >> 6;
  if (tid < 128){
    int k = tid & 63;
    const float* hv = (tid < 64) ? pW : vW;
    const float* row = W2 + k*64;
    float acc = 0.f;
    #pragma unroll 16
    for (int c = 0; c < 64; c++) acc += row[c]*hv[c];
    if (tid < 64) sq[k] = acc; else sv[k] = acc;
  } else if (tid == 128){
    float a = 0.f, c = 0.f;
    #pragma unroll 16
    for (int jj = 0; jj < 64; jj++){ a += b2[jj]*pW[jj]; c += b2[jj]*vW[jj]; }
    scst[0] = a + pb[0];
    scst[1] = c + vb[0];
  }
  ull wp[34];
  #pragma unroll
  for (int k2 = 0; k2 < 34; k2++)
    wp[k2] = pk2(W[(2*k2)*64 + j], W[(2*k2+1)*64 + j]);
  float w68 = W[68*64 + j];
  float bj = b[j];
  float4 sc4, sh4;
  if (j < 16){
    sc4 = ((const float4*)g_bnscale)[j];
    sh4 = ((const float4*)g_bnshift)[j];
  }
  for (int n0 = blockIdx.x*4; n0 < NN; n0 += gridDim.x*4){
    int n = n0 + g;
    if (n < NN){
      if (j < 16){
        float4 v = ((const float4*)(g_buf64 + (size_t)n*64))[j];
        v.x = fmaxf(fmaf(v.x, sc4.x, sh4.x), 0.f);
        v.y = fmaxf(fmaf(v.y, sc4.y, sh4.y), 0.f);
        v.z = fmaxf(fmaf(v.z, sc4.z, sh4.z), 0.f);
        v.w = fmaxf(fmaf(v.w, sc4.w, sh4.w), 0.f);
        ((float4*)sh[g])[j] = v;
      }
      if (j >= 16 && j < 21) sh[g][48 + j] = x[(size_t)n*16 + (j - 7)];  // ctx = x[:,9:14]
    }
    __syncthreads();
    float lp = 0.f, vp = 0.f;
    {
      ull a0 = 0ull, a1 = 0ull;
      const ull* yp = (const ull*)sh[g];
      #pragma unroll
      for (int k2 = 0; k2 < 34; k2 += 2){
        FMA2(a0, yp[k2],   wp[k2],   a0);
        FMA2(a1, yp[k2+1], wp[k2+1], a1);
      }
      float l0,h0,l1,h1; upk2(l0,h0,a0); upk2(l1,h1,a1);
      float t = fmaxf((l0+h0)+(l1+h1) + sh[g][68]*w68 + bj, 0.f);
      if (n < NN){ lp = t*sq[j]; vp = t*sv[j]; }
    }
    #pragma unroll
    for (int o = 16; o; o >>= 1){
      lp += __shfl_xor_sync(0xffffffffu, lp, o);
      vp += __shfl_xor_sync(0xffffffffu, vp, o);
    }
    int w = tid >> 5;
    if ((tid & 31) == 0){ spart[w][0] = lp; spart[w][1] = vp; }
    __syncthreads();
    if (tid < 4){
      int nn = n0 + tid;
      if (nn < NN){
        out[nn]      = spart[2*tid][0] + spart[2*tid+1][0] + scst[0];
        out[NN + nn] = spart[2*tid][1] + spart[2*tid+1][1] + scst[1];
      }
    }
    __syncthreads();
  }
}

// ---------------- launch -----------------------------------------------------
extern "C" void kernel_launch(void* const* d_in, const int* in_sizes, int n_in,
                              void* d_out, int out_size){
  const float* x   = (const float*)d_in[0];
  const int*   ei  = (const int*)  d_in[1];
  const float* W1  = (const float*)d_in[2];
  const float* as1 = (const float*)d_in[3];
  const float* ad1 = (const float*)d_in[4];
  const float* b1  = (const float*)d_in[5];
  const float* g1  = (const float*)d_in[6];
  const float* be1 = (const float*)d_in[7];
  const float* W2  = (const float*)d_in[8];
  const float* as2 = (const float*)d_in[9];
  const float* ad2 = (const float*)d_in[10];
  const float* b2  = (const float*)d_in[11];
  const float* g2  = (const float*)d_in[12];
  const float* be2 = (const float*)d_in[13];
  const float* W3  = (const float*)d_in[14];
  const float* as3 = (const float*)d_in[15];
  const float* ad3 = (const float*)d_in[16];
  const float* b3  = (const float*)d_in[17];
  const float* g3  = (const float*)d_in[18];
  const float* be3 = (const float*)d_in[19];
  const float* mW1 = (const float*)d_in[20];
  const float* mb1 = (const float*)d_in[21];
  const float* mW2 = (const float*)d_in[22];
  const float* mb2 = (const float*)d_in[23];
  const float* pW  = (const float*)d_in[24];
  const float* pb  = (const float*)d_in[25];
  const float* vW  = (const float*)d_in[26];
  const float* vb  = (const float*)d_in[27];
  float* out = (float*)d_out;

  const int TB = 256;
  const int gE    = (EE + TB - 1)/TB;
  const int gN    = (NN + TB - 1)/TB;
  const int gWarp = (NN*32 + TB - 1)/TB;
  const int gMlp  = 1184;

  // CSR + att1 (k_att1 at launch index 3 so ncu profiles it)
  k_count<<<gE, TB>>>(ei);
  k_scan1<<<NB1, TB>>>();
  k_scan23c<<<NB1, TB>>>();
  k_att1<<<gN, TB>>>(x, W1, as1, ad1);
  k_scatter<<<gE, TB>>>(ei);

  // layer 1 (D=16, raw x, no BN)
  k_aggregate<16,false><<<gWarp, TB>>>(x);
  k_out<16><<<GOUT, TB>>>(W1, b1, g1, be1);

  // layer 2 (D=64, BN folded into gather)
  k_att2<<<gN, TB>>>(W2, as2, ad2);
  k_aggregate<64,true><<<gWarp, TB>>>(nullptr);
  k_out<64><<<GOUT, TB>>>(W2, b2, g2, be2);

  // layer 3
  k_att2<<<gN, TB>>>(W3, as3, ad3);
  k_aggregate<64,true><<<gWarp, TB>>>(nullptr);
  k_out<64><<<GOUT, TB>>>(W3, b3, g3, be3);

  // MLP + heads (fused)
  k_mlp1h<<<gMlp, TB>>>(x, mW1, mb1, mW2, mb2, pW, pb, vW, vb, out);
}

// round 9
// speedup vs baseline: 1.2840x; 1.0153x over previous
#include <cuda_runtime.h>
#include <math.h>

#define NN 100000
#define EE 1000000
#define NB1 98     // ceil(NN/1024)
#define GOUT 592   // grid for k_out

typedef unsigned long long ull;

// ---------------- scratch (static device globals; no allocation) -------------
__device__ float  g_z[(size_t)NN*128];     // aggregated per-head features
__device__ float  g_buf64[(size_t)NN*64];  // layer output (pre-BN)
__device__ float  g_as[NN*2];              // per-node src scores
__device__ float4 g_att[NN];               // (as0, as1, ad0, ad1) per node
__device__ int    g_deg[NN];               // zero-init; re-zeroed by k_scatter
__device__ int    g_off[NN];
__device__ int    g_cursor[NN];
__device__ int    g_esrc[EE];
__device__ int    g_bsum[128];
__device__ float  g_part[GOUT*128];        // BN partials per k_out block
__device__ float  g_bnscale[64];
__device__ float  g_bnshift[64];
__device__ int    g_bncnt;

__device__ __forceinline__ float lrelu(float v){ return v > 0.f ? v : 0.2f*v; }

__device__ __forceinline__ ull pk2(float lo, float hi){
  ull u; asm("mov.b64 %0, {%1, %2};" : "=l"(u) : "f"(lo), "f"(hi)); return u;
}
__device__ __forceinline__ void upk2(float& lo, float& hi, ull u){
  asm("mov.b64 {%0, %1}, %2;" : "=f"(lo), "=f"(hi) : "l"(u));
}
#define FMA2(d, a, b, c) \
  asm("fma.rn.f32x2 %0, %1, %2, %3;" : "=l"(d) : "l"(a), "l"(b), "l"(c))

// ---------------- CSR build --------------------------------------------------
__global__ void k_count(const int* __restrict__ ei){
  int e = blockIdx.x*blockDim.x + threadIdx.x;
  if (e < EE) atomicAdd(&g_deg[ei[EE + e]], 1);
}

__global__ void k_scan1(){
  __shared__ int s[256];
  int tid = threadIdx.x;
  int base = blockIdx.x*1024 + tid*4;
  int v[4]; int loc = 0;
  #pragma unroll
  for (int i = 0; i < 4; i++){ int idx = base + i; v[i] = (idx < NN) ? g_deg[idx] : 0; loc += v[i]; }
  s[tid] = loc; __syncthreads();
  #pragma unroll
  for (int d = 1; d < 256; d <<= 1){
    int t = (tid >= d) ? s[tid-d] : 0; __syncthreads();
    s[tid] += t; __syncthreads();
  }
  int run = (tid == 0) ? 0 : s[tid-1];
  #pragma unroll
  for (int i = 0; i < 4; i++){ run += v[i]; int idx = base + i; if (idx < NN) g_off[idx] = run; }
  if (tid == 255) g_bsum[blockIdx.x] = s[255];
}

__global__ void k_scan23c(){
  int tid = threadIdx.x;
  int b = blockIdx.x;
  __shared__ int swarp[8];
  int v = (tid < b) ? g_bsum[tid] : 0;     // b <= 97 < 128
  #pragma unroll
  for (int o = 16; o; o >>= 1) v += __shfl_xor_sync(0xffffffffu, v, o);
  if ((tid & 31) == 0) swarp[tid >> 5] = v;
  __syncthreads();
  int pre = swarp[0] + swarp[1] + swarp[2] + swarp[3];
  int base = b*1024 + tid*4;
  #pragma unroll
  for (int i = 0; i < 4; i++){
    int idx = base + i;
    if (idx < NN){
      int off = g_off[idx] + pre;
      g_off[idx] = off;
      g_cursor[idx] = off - g_deg[idx];
    }
  }
}

__global__ void k_scatter(const int* __restrict__ ei){
  int e = blockIdx.x*blockDim.x + threadIdx.x;
  if (e < EE){
    int s = ei[e], d = ei[EE + e];
    int pos = atomicAdd(&g_cursor[d], 1);
    g_esrc[pos] = s;
  }
  if (e < NN) g_deg[e] = 0;   // re-zero for next replay (deg is dead by now)
}

// ---------------- attention scores (layer 1): thread-per-node ----------------
__global__ void __launch_bounds__(256) k_att1(const float* __restrict__ x,
                                              const float* __restrict__ W,
                                              const float* __restrict__ as_,
                                              const float* __restrict__ ad_){
  __shared__ float swa[2][16], swd[2][16];
  int tid = threadIdx.x;
  if (tid < 64){
    int h = (tid >> 4) & 1;
    int k = tid & 15;
    const float* att = (tid < 32) ? as_ : ad_;
    const float* wrow = W + k*128 + h*64;
    float acc = 0.f;
    #pragma unroll 16
    for (int c = 0; c < 64; c++) acc += wrow[c]*att[h*64 + c];
    if (tid < 32) swa[h][k] = acc; else swd[h][k] = acc;
  }
  __syncthreads();
  int n = blockIdx.x*blockDim.x + tid;
  if (n >= NN) return;
  float s0 = 0.f, s1 = 0.f, d0 = 0.f, d1 = 0.f;
  const float4* xr = (const float4*)(x + (size_t)n*16);
  #pragma unroll
  for (int q = 0; q < 4; q++){
    float4 v = xr[q];
    int k = 4*q;
    s0 += v.x*swa[0][k] + v.y*swa[0][k+1] + v.z*swa[0][k+2] + v.w*swa[0][k+3];
    s1 += v.x*swa[1][k] + v.y*swa[1][k+1] + v.z*swa[1][k+2] + v.w*swa[1][k+3];
    d0 += v.x*swd[0][k] + v.y*swd[0][k+1] + v.z*swd[0][k+2] + v.w*swd[0][k+3];
    d1 += v.x*swd[1][k] + v.y*swd[1][k+1] + v.z*swd[1][k+2] + v.w*swd[1][k+3];
  }
  ((float2*)g_as)[n] = make_float2(s0, s1);
  g_att[n] = make_float4(s0, s1, d0, d1);
}

// ---------------- attention scores (layers 2,3): thread-per-node, BN in regs -
__global__ void __launch_bounds__(256) k_att2(const float* __restrict__ W,
                                              const float* __restrict__ as_,
                                              const float* __restrict__ ad_){
  __shared__ float swa[2][64], swd[2][64];
  __shared__ float sbs[64], sbh[64];
  int tid = threadIdx.x;
  {
    int h = (tid >> 6) & 1;
    int k = tid & 63;
    const float* att = (tid < 128) ? as_ : ad_;
    const float* wrow = W + k*128 + h*64;
    float acc = 0.f;
    #pragma unroll 16
    for (int c = 0; c < 64; c++) acc += wrow[c]*att[h*64 + c];
    if (tid < 128) swa[h][k] = acc; else swd[h][k] = acc;
    if (tid < 64){ sbs[tid] = g_bnscale[tid]; sbh[tid] = g_bnshift[tid]; }
  }
  __syncthreads();
  int n = blockIdx.x*blockDim.x + tid;
  if (n >= NN) return;
  float s0 = 0.f, s1 = 0.f, d0 = 0.f, d1 = 0.f;
  const float4* xr = (const float4*)(g_buf64 + (size_t)n*64);
  #pragma unroll
  for (int q = 0; q < 16; q++){
    float4 v = xr[q];
    int k = 4*q;
    v.x = fmaxf(fmaf(v.x, sbs[k],   sbh[k]),   0.f);
    v.y = fmaxf(fmaf(v.y, sbs[k+1], sbh[k+1]), 0.f);
    v.z = fmaxf(fmaf(v.z, sbs[k+2], sbh[k+2]), 0.f);
    v.w = fmaxf(fmaf(v.w, sbs[k+3], sbh[k+3]), 0.f);
    s0 += v.x*swa[0][k] + v.y*swa[0][k+1] + v.z*swa[0][k+2] + v.w*swa[0][k+3];
    s1 += v.x*swa[1][k] + v.y*swa[1][k+1] + v.z*swa[1][k+2] + v.w*swa[1][k+3];
    d0 += v.x*swd[0][k] + v.y*swd[0][k+1] + v.z*swd[0][k+2] + v.w*swd[0][k+3];
    d1 += v.x*swd[1][k] + v.y*swd[1][k+1] + v.z*swd[1][k+2] + v.w*swd[1][k+3];
  }
  ((float2*)g_as)[n] = make_float2(s0, s1);
  g_att[n] = make_float4(s0, s1, d0, d1);
}

// ---------------- GAT aggregation: 16-lane group per node --------------------
// NOTE: the two 16-lane groups of a warp process different nodes -> divergent
// loop trip counts. Every shuffle uses the group's own 16-lane mask.
// Layer 1 (D=16): lane holds 1 channel; raw x input, no BN.
__global__ void __launch_bounds__(256) k_agg16(const float* __restrict__ x){
  int t = blockIdx.x*blockDim.x + threadIdx.x;
  int n = t >> 4, lane = t & 15;
  if (n >= NN) return;
  const unsigned gm = 0xFFFFu << (threadIdx.x & 16);   // this group's mask
  int start = n ? g_off[n-1] : 0;
  int end   = g_off[n];
  int len   = end - start;
  float4 attn = g_att[n];
  float ad0 = attn.z, ad1 = attn.w;
  float es0 = lrelu(attn.x + ad0);
  float es1 = lrelu(attn.y + ad1);
  float vs = x[(size_t)n*16 + lane];
  float y0, y1, den0, den1;

  if (len <= 16){
    int s = 0; float e0 = -1e30f, e1 = -1e30f;
    if (lane < len){
      s = g_esrc[start + lane];
      float2 a = ((const float2*)g_as)[s];
      e0 = lrelu(a.x + ad0);
      e1 = lrelu(a.y + ad1);
    }
    float m0 = fmaxf(e0, es0), m1 = fmaxf(e1, es1);
    #pragma unroll
    for (int o = 8; o; o >>= 1){
      m0 = fmaxf(m0, __shfl_xor_sync(gm, m0, o, 16));
      m1 = fmaxf(m1, __shfl_xor_sync(gm, m1, o, 16));
    }
    float w0 = (lane < len) ? __expf(e0 - m0) : 0.f;
    float w1 = (lane < len) ? __expf(e1 - m1) : 0.f;
    float d0 = w0, d1 = w1;
    #pragma unroll
    for (int o = 8; o; o >>= 1){
      d0 += __shfl_xor_sync(gm, d0, o, 16);
      d1 += __shfl_xor_sync(gm, d1, o, 16);
    }
    float ws0 = __expf(es0 - m0), ws1 = __expf(es1 - m1);
    den0 = d0 + ws0 + 1e-16f;
    den1 = d1 + ws1 + 1e-16f;
    y0 = ws0*vs; y1 = ws1*vs;
    #pragma unroll 4
    for (int k = 0; k < len; k++){
      int   sk  = __shfl_sync(gm, s,  k, 16);
      float wk0 = __shfl_sync(gm, w0, k, 16);
      float wk1 = __shfl_sync(gm, w1, k, 16);
      float v = x[(size_t)sk*16 + lane];
      y0 += wk0*v; y1 += wk1*v;
    }
  } else {
    float m0 = es0, m1 = es1;
    for (int i = start + lane; i < end; i += 16){
      int s = g_esrc[i];
      float2 a = ((const float2*)g_as)[s];
      m0 = fmaxf(m0, lrelu(a.x + ad0));
      m1 = fmaxf(m1, lrelu(a.y + ad1));
    }
    #pragma unroll
    for (int o = 8; o; o >>= 1){
      m0 = fmaxf(m0, __shfl_xor_sync(gm, m0, o, 16));
      m1 = fmaxf(m1, __shfl_xor_sync(gm, m1, o, 16));
    }
    float ws0 = __expf(es0 - m0), ws1 = __expf(es1 - m1);
    y0 = ws0*vs; y1 = ws1*vs;
    float d0 = 0.f, d1 = 0.f;
    for (int base = start; base < end; base += 16){
      int cnt = min(16, end - base);
      int s = 0; float w0 = 0.f, w1 = 0.f;
      if (lane < cnt){
        s = g_esrc[base + lane];
        float2 a = ((const float2*)g_as)[s];
        w0 = __expf(lrelu(a.x + ad0) - m0);
        w1 = __expf(lrelu(a.y + ad1) - m1);
      }
      d0 += w0; d1 += w1;
      for (int k = 0; k < cnt; k++){
        int   sk  = __shfl_sync(gm, s,  k, 16);
        float wk0 = __shfl_sync(gm, w0, k, 16);
        float wk1 = __shfl_sync(gm, w1, k, 16);
        float v = x[(size_t)sk*16 + lane];
        y0 += wk0*v; y1 += wk1*v;
      }
    }
    #pragma unroll
    for (int o = 8; o; o >>= 1){
      d0 += __shfl_xor_sync(gm, d0, o, 16);
      d1 += __shfl_xor_sync(gm, d1, o, 16);
    }
    den0 = d0 + ws0 + 1e-16f;
    den1 = d1 + ws1 + 1e-16f;
  }

  float* zr = g_z + (size_t)n*32;
  zr[lane]      = y0/den0;
  zr[16 + lane] = y1/den1;
}

// Layers 2,3 (D=64): lane holds 4 channels (float4); BN+relu folded into gather.
__global__ void __launch_bounds__(256) k_agg64(){
  int t = blockIdx.x*blockDim.x + threadIdx.x;
  int n = t >> 4, lane = t & 15;
  if (n >= NN) return;
  const unsigned gm = 0xFFFFu << (threadIdx.x & 16);   // this group's mask
  float4 sc4 = ((const float4*)g_bnscale)[lane];
  float4 sh4 = ((const float4*)g_bnshift)[lane];
  int start = n ? g_off[n-1] : 0;
  int end   = g_off[n];
  int len   = end - start;
  float4 attn = g_att[n];
  float ad0 = attn.z, ad1 = attn.w;
  float es0 = lrelu(attn.x + ad0);
  float es1 = lrelu(attn.y + ad1);
  float4 vs = ((const float4*)(g_buf64 + (size_t)n*64))[lane];
  vs.x = fmaxf(fmaf(vs.x, sc4.x, sh4.x), 0.f);
  vs.y = fmaxf(fmaf(vs.y, sc4.y, sh4.y), 0.f);
  vs.z = fmaxf(fmaf(vs.z, sc4.z, sh4.z), 0.f);
  vs.w = fmaxf(fmaf(vs.w, sc4.w, sh4.w), 0.f);
  float4 y0, y1;
  float den0, den1;

  if (len <= 16){
    int s = 0; float e0 = -1e30f, e1 = -1e30f;
    if (lane < len){
      s = g_esrc[start + lane];
      float2 a = ((const float2*)g_as)[s];
      e0 = lrelu(a.x + ad0);
      e1 = lrelu(a.y + ad1);
    }
    float m0 = fmaxf(e0, es0), m1 = fmaxf(e1, es1);
    #pragma unroll
    for (int o = 8; o; o >>= 1){
      m0 = fmaxf(m0, __shfl_xor_sync(gm, m0, o, 16));
      m1 = fmaxf(m1, __shfl_xor_sync(gm, m1, o, 16));
    }
    float w0 = (lane < len) ? __expf(e0 - m0) : 0.f;
    float w1 = (lane < len) ? __expf(e1 - m1) : 0.f;
    float d0 = w0, d1 = w1;
    #pragma unroll
    for (int o = 8; o; o >>= 1){
      d0 += __shfl_xor_sync(gm, d0, o, 16);
      d1 += __shfl_xor_sync(gm, d1, o, 16);
    }
    float ws0 = __expf(es0 - m0), ws1 = __expf(es1 - m1);
    den0 = d0 + ws0 + 1e-16f;
    den1 = d1 + ws1 + 1e-16f;
    y0.x = ws0*vs.x; y0.y = ws0*vs.y; y0.z = ws0*vs.z; y0.w = ws0*vs.w;
    y1.x = ws1*vs.x; y1.y = ws1*vs.y; y1.z = ws1*vs.z; y1.w = ws1*vs.w;
    #pragma unroll 4
    for (int k = 0; k < len; k++){
      int   sk  = __shfl_sync(gm, s,  k, 16);
      float wk0 = __shfl_sync(gm, w0, k, 16);
      float wk1 = __shfl_sync(gm, w1, k, 16);
      float4 v = ((const float4*)(g_buf64 + (size_t)sk*64))[lane];
      v.x = fmaxf(fmaf(v.x, sc4.x, sh4.x), 0.f);
      v.y = fmaxf(fmaf(v.y, sc4.y, sh4.y), 0.f);
      v.z = fmaxf(fmaf(v.z, sc4.z, sh4.z), 0.f);
      v.w = fmaxf(fmaf(v.w, sc4.w, sh4.w), 0.f);
      y0.x += wk0*v.x; y0.y += wk0*v.y; y0.z += wk0*v.z; y0.w += wk0*v.w;
      y1.x += wk1*v.x; y1.y += wk1*v.y; y1.z += wk1*v.z; y1.w += wk1*v.w;
    }
  } else {
    float m0 = es0, m1 = es1;
    for (int i = start + lane; i < end; i += 16){
      int s = g_esrc[i];
      float2 a = ((const float2*)g_as)[s];
      m0 = fmaxf(m0, lrelu(a.x + ad0));
      m1 = fmaxf(m1, lrelu(a.y + ad1));
    }
    #pragma unroll
    for (int o = 8; o; o >>= 1){
      m0 = fmaxf(m0, __shfl_xor_sync(gm, m0, o, 16));
      m1 = fmaxf(m1, __shfl_xor_sync(gm, m1, o, 16));
    }
    float ws0 = __expf(es0 - m0), ws1 = __expf(es1 - m1);
    y0.x = ws0*vs.x; y0.y = ws0*vs.y; y0.z = ws0*vs.z; y0.w = ws0*vs.w;
    y1.x = ws1*vs.x; y1.y = ws1*vs.y; y1.z = ws1*vs.z; y1.w = ws1*vs.w;
    float d0 = 0.f, d1 = 0.f;
    for (int base = start; base < end; base += 16){
      int cnt = min(16, end - base);
      int s = 0; float w0 = 0.f, w1 = 0.f;
      if (lane < cnt){
        s = g_esrc[base + lane];
        float2 a = ((const float2*)g_as)[s];
        w0 = __expf(lrelu(a.x + ad0) - m0);
        w1 = __expf(lrelu(a.y + ad1) - m1);
      }
      d0 += w0; d1 += w1;
      for (int k = 0; k < cnt; k++){
        int   sk  = __shfl_sync(gm, s,  k, 16);
        float wk0 = __shfl_sync(gm, w0, k, 16);
        float wk1 = __shfl_sync(gm, w1, k, 16);
        float4 v = ((const float4*)(g_buf64 + (size_t)sk*64))[lane];
        v.x = fmaxf(fmaf(v.x, sc4.x, sh4.x), 0.f);
        v.y = fmaxf(fmaf(v.y, sc4.y, sh4.y), 0.f);
        v.z = fmaxf(fmaf(v.z, sc4.z, sh4.z), 0.f);
        v.w = fmaxf(fmaf(v.w, sc4.w, sh4.w), 0.f);
        y0.x += wk0*v.x; y0.y += wk0*v.y; y0.z += wk0*v.z; y0.w += wk0*v.w;
        y1.x += wk1*v.x; y1.y += wk1*v.y; y1.z += wk1*v.z; y1.w += wk1*v.w;
      }
    }
    #pragma unroll
    for (int o = 8; o; o >>= 1){
      d0 += __shfl_xor_sync(gm, d0, o, 16);
      d1 += __shfl_xor_sync(gm, d1, o, 16);
    }
    den0 = d0 + ws0 + 1e-16f;
    den1 = d1 + ws1 + 1e-16f;
  }

  float i0 = 1.f/den0, i1 = 1.f/den1;
  float4* zr = (float4*)(g_z + (size_t)n*128);
  zr[lane]      = make_float4(y0.x*i0, y0.y*i0, y0.z*i0, y0.w*i0);
  zr[16 + lane] = make_float4(y1.x*i1, y1.y*i1, y1.z*i1, y1.w*i1);
}

// ---------------- output transform: 8 nodes per barrier pair -----------------
template<int D>
__global__ void __launch_bounds__(256) k_out(const float* __restrict__ W,
                                             const float* __restrict__ b,
                                             const float* __restrict__ gam,
                                             const float* __restrict__ bet){
  int tid = threadIdx.x;
  int g   = tid >> 7;
  int idx = tid & 127;
  int j   = idx >> 1;
  int hb  = idx & 1;
  ull wp[D/2];
  #pragma unroll
  for (int k2 = 0; k2 < D/2; k2++)
    wp[k2] = pk2(0.5f*W[(2*k2)*128 + hb*64 + j], 0.5f*W[(2*k2+1)*128 + hb*64 + j]);
  float bj = b[j];
  __shared__ __align__(16) float sy[8][2*D];
  __shared__ float sacc[256];
  float bs = 0.f, bq = 0.f;
  const int F4 = D/2;                  // float4 per row
  for (int n0 = blockIdx.x*8; n0 < NN; n0 += GOUT*8){
    if (tid < 4*D){
      int row = tid / F4;
      int col = tid % F4;
      int n = n0 + row;
      if (n < NN)
        ((float4*)sy[row])[col] = ((const float4*)(g_z + (size_t)n*(2*D)))[col];
    }
    __syncthreads();
    #pragma unroll
    for (int i = 0; i < 4; i++){
      int n = n0 + g*4 + i;
      const ull* yp = (const ull*)(sy[g*4+i] + hb*D);
      ull a0 = 0ull, a1 = 0ull;
      #pragma unroll
      for (int k2 = 0; k2 < D/2; k2 += 2){
        FMA2(a0, yp[k2],   wp[k2],   a0);
        FMA2(a1, yp[k2+1], wp[k2+1], a1);
      }
      float l0,h0,l1,h1; upk2(l0,h0,a0); upk2(l1,h1,a1);
      float partial = (l0+h0)+(l1+h1);
      float comb = partial + __shfl_xor_sync(0xffffffffu, partial, 1);
      if (hb == 0 && n < NN){
        float r = comb + bj;
        g_buf64[(size_t)n*64 + j] = r;
        bs += r; bq += r*r;
      }
    }
    __syncthreads();
  }
  sacc[tid] = bs;
  __syncthreads();
  float ts = 0.f;
  if (tid < 64) ts = sacc[2*tid] + sacc[128 + 2*tid];
  __syncthreads();
  sacc[tid] = bq;
  __syncthreads();
  if (tid < 64){
    g_part[blockIdx.x*128 + tid]      = ts;
    g_part[blockIdx.x*128 + 64 + tid] = sacc[2*tid] + sacc[128 + 2*tid];
  }
  __threadfence();
  __shared__ bool lastb;
  if (tid == 0){
    lastb = (atomicAdd(&g_bncnt, 1) == GOUT-1);
    if (lastb) g_bncnt = 0;
  }
  __syncthreads();
  if (lastb && tid < 64){
    float ss = 0.f, qq = 0.f;
    #pragma unroll 8
    for (int bb = 0; bb < GOUT; bb++){
      ss += __ldcg(&g_part[bb*128 + tid]);
      qq += __ldcg(&g_part[bb*128 + 64 + tid]);
    }
    const float inv = 1.f/(float)NN;
    float mean = ss*inv;
    float var  = qq*inv - mean*mean;
    float rstd = rsqrtf(var + 1e-5f);
    float scv = rstd*gam[tid];
    g_bnscale[tid] = scv;
    g_bnshift[tid] = bet[tid] - mean*scv;
  }
}

// ---------------- MLP1 + heads fused (BN3 at load, hidden never stored) ------
__global__ void __launch_bounds__(256) k_mlp1h(const float* __restrict__ x,
                                               const float* __restrict__ W,
                                               const float* __restrict__ b,
                                               const float* __restrict__ W2,
                                               const float* __restrict__ b2,
                                               const float* __restrict__ pW,
                                               const float* __restrict__ pb,
                                               const float* __restrict__ vW,
                                               const float* __restrict__ vb,
                                               float* __restrict__ out){
  __shared__ float sq[64], sv[64], scst[2];
  __shared__ __align__(16) float sh[4][72];
  __shared__ float spart[8][2];
  int tid = threadIdx.x;
  int j = tid & 63, g = tid >> 6;
  if (tid < 128){
    int k = tid & 63;
    const float* hv = (tid < 64) ? pW : vW;
    const float* row = W2 + k*64;
    float acc = 0.f;
    #pragma unroll 16
    for (int c = 0; c < 64; c++) acc += row[c]*hv[c];
    if (tid < 64) sq[k] = acc; else sv[k] = acc;
  } else if (tid == 128){
    float a = 0.f, c = 0.f;
    #pragma unroll 16
    for (int jj = 0; jj < 64; jj++){ a += b2[jj]*pW[jj]; c += b2[jj]*vW[jj]; }
    scst[0] = a + pb[0];
    scst[1] = c + vb[0];
  }
  ull wp[34];
  #pragma unroll
  for (int k2 = 0; k2 < 34; k2++)
    wp[k2] = pk2(W[(2*k2)*64 + j], W[(2*k2+1)*64 + j]);
  float w68 = W[68*64 + j];
  float bj = b[j];
  float4 sc4, sh4;
  if (j < 16){
    sc4 = ((const float4*)g_bnscale)[j];
    sh4 = ((const float4*)g_bnshift)[j];
  }
  for (int n0 = blockIdx.x*4; n0 < NN; n0 += gridDim.x*4){
    int n = n0 + g;
    if (n < NN){
      if (j < 16){
        float4 v = ((const float4*)(g_buf64 + (size_t)n*64))[j];
        v.x = fmaxf(fmaf(v.x, sc4.x, sh4.x), 0.f);
        v.y = fmaxf(fmaf(v.y, sc4.y, sh4.y), 0.f);
        v.z = fmaxf(fmaf(v.z, sc4.z, sh4.z), 0.f);
        v.w = fmaxf(fmaf(v.w, sc4.w, sh4.w), 0.f);
        ((float4*)sh[g])[j] = v;
      }
      if (j >= 16 && j < 21) sh[g][48 + j] = x[(size_t)n*16 + (j - 7)];  // ctx = x[:,9:14]
    }
    __syncthreads();
    float lp = 0.f, vp = 0.f;
    {
      ull a0 = 0ull, a1 = 0ull;
      const ull* yp = (const ull*)sh[g];
      #pragma unroll
      for (int k2 = 0; k2 < 34; k2 += 2){
        FMA2(a0, yp[k2],   wp[k2],   a0);
        FMA2(a1, yp[k2+1], wp[k2+1], a1);
      }
      float l0,h0,l1,h1; upk2(l0,h0,a0); upk2(l1,h1,a1);
      float t = fmaxf((l0+h0)+(l1+h1) + sh[g][68]*w68 + bj, 0.f);
      if (n < NN){ lp = t*sq[j]; vp = t*sv[j]; }
    }
    #pragma unroll
    for (int o = 16; o; o >>= 1){
      lp += __shfl_xor_sync(0xffffffffu, lp, o);
      vp += __shfl_xor_sync(0xffffffffu, vp, o);
    }
    int w = tid >> 5;
    if ((tid & 31) == 0){ spart[w][0] = lp; spart[w][1] = vp; }
    __syncthreads();
    if (tid < 4){
      int nn = n0 + tid;
      if (nn < NN){
        out[nn]      = spart[2*tid][0] + spart[2*tid+1][0] + scst[0];
        out[NN + nn] = spart[2*tid][1] + spart[2*tid+1][1] + scst[1];
      }
    }
    __syncthreads();
  }
}

// ---------------- launch -----------------------------------------------------
extern "C" void kernel_launch(void* const* d_in, const int* in_sizes, int n_in,
                              void* d_out, int out_size){
  const float* x   = (const float*)d_in[0];
  const int*   ei  = (const int*)  d_in[1];
  const float* W1  = (const float*)d_in[2];
  const float* as1 = (const float*)d_in[3];
  const float* ad1 = (const float*)d_in[4];
  const float* b1  = (const float*)d_in[5];
  const float* g1  = (const float*)d_in[6];
  const float* be1 = (const float*)d_in[7];
  const float* W2  = (const float*)d_in[8];
  const float* as2 = (const float*)d_in[9];
  const float* ad2 = (const float*)d_in[10];
  const float* b2  = (const float*)d_in[11];
  const float* g2  = (const float*)d_in[12];
  const float* be2 = (const float*)d_in[13];
  const float* W3  = (const float*)d_in[14];
  const float* as3 = (const float*)d_in[15];
  const float* ad3 = (const float*)d_in[16];
  const float* b3  = (const float*)d_in[17];
  const float* g3  = (const float*)d_in[18];
  const float* be3 = (const float*)d_in[19];
  const float* mW1 = (const float*)d_in[20];
  const float* mb1 = (const float*)d_in[21];
  const float* mW2 = (const float*)d_in[22];
  const float* mb2 = (const float*)d_in[23];
  const float* pW  = (const float*)d_in[24];
  const float* pb  = (const float*)d_in[25];
  const float* vW  = (const float*)d_in[26];
  const float* vb  = (const float*)d_in[27];
  float* out = (float*)d_out;

  const int TB = 256;
  const int gE   = (EE + TB - 1)/TB;
  const int gN   = (NN + TB - 1)/TB;
  const int gGrp = (NN*16 + TB - 1)/TB;   // 16-lane group per node
  const int gMlp = 1184;

  // CSR + att1 (k_att1 at launch index 3 so ncu profiles it)
  k_count<<<gE, TB>>>(ei);
  k_scan1<<<NB1, TB>>>();
  k_scan23c<<<NB1, TB>>>();
  k_att1<<<gN, TB>>>(x, W1, as1, ad1);
  k_scatter<<<gE, TB>>>(ei);

  // layer 1 (D=16, raw x, no BN)
  k_agg16<<<gGrp, TB>>>(x);
  k_out<16><<<GOUT, TB>>>(W1, b1, g1, be1);

  // layer 2 (D=64, BN folded into gather)
  k_att2<<<gN, TB>>>(W2, as2, ad2);
  k_agg64<<<gGrp, TB>>>();
  k_out<64><<<GOUT, TB>>>(W2, b2, g2, be2);

  // layer 3
  k_att2<<<gN, TB>>>(W3, as3, ad3);
  k_agg64<<<gGrp, TB>>>();
  k_out<64><<<GOUT, TB>>>(W3, b3, g3, be3);

  // MLP + heads (fused)
  k_mlp1h<<<gMlp, TB>>>(x, mW1, mb1, mW2, mb2, pW, pb, vW, vb, out);
}